// round 9
// baseline (speedup 1.0000x reference)
#include <cuda_runtime.h>
#include <cuda_bf16.h>
#include <cstdint>

#define EPSm   1e-5f
#define NROWSm 131072
#define NTILESm 2048          // 64-row tiles
#define NPART  2048

// ---------------- device scratch ----------------
__device__ float g_x[NROWSm * 128];
__device__ float g_part[NPART * 128 * 128];   // 128 MB gram partials (stage 0)
__device__ float g_part2[64 * 128 * 128];     // 4 MB (stage 1)
__device__ float g_QK[128 * 128];
__device__ float g_T1[128 * 128];
__device__ __nv_bfloat16 g_Mt_hi[128 * 128],  g_Mt_lo[128 * 128];
__device__ __nv_bfloat16 g_w1t_hi[512 * 128], g_w1t_lo[512 * 128];   // [512 n][128 k]
__device__ __nv_bfloat16 g_w2t_hi[128 * 512], g_w2t_lo[128 * 512];   // [128 n][512 k]
__device__ __nv_bfloat16 g_owt_hi[128 * 128], g_owt_lo[128 * 128];

// ---------------- helpers ----------------
__device__ __forceinline__ uint32_t smem_u32(const void* p) {
    uint32_t a;
    asm("{ .reg .u64 t; cvta.to.shared.u64 t, %1; cvt.u32.u64 %0, t; }" : "=r"(a) : "l"(p));
    return a;
}
// XOR-swizzled tile, 256B rows (128 bf16 cols)
__device__ __forceinline__ uint32_t sw16(int r, int c8) {
    return (uint32_t)(r * 256 + ((c8 ^ (r & 7)) << 4));
}
__device__ __forceinline__ uint32_t sw4(int r, int col) {
    return (uint32_t)(r * 256 + ((((col >> 3) ^ (r & 7)) << 4)) + (col & 7) * 2);
}
// XOR-swizzled tile, 64B rows (32 bf16 cols) — minimum 2-way conflicts
__device__ __forceinline__ uint32_t sw16_32(int r, int c8) {
    return (uint32_t)(r * 64 + ((((c8 ^ (r & 3)) & 3) << 4)));
}
__device__ __forceinline__ uint32_t sw4_32(int r, int col) {
    return (uint32_t)(r * 64 + ((((col >> 3) ^ (r & 3)) & 3) << 4) + (col & 7) * 2);
}
__device__ __forceinline__ void split2(float f0, float f1, uint32_t& hi, uint32_t& lo) {
    __nv_bfloat162 H = __floats2bfloat162_rn(f0, f1);
    float r0 = f0 - __bfloat162float(H.x);
    float r1 = f1 - __bfloat162float(H.y);
    __nv_bfloat162 L = __floats2bfloat162_rn(r0, r1);
    hi = *reinterpret_cast<uint32_t*>(&H);
    lo = *reinterpret_cast<uint32_t*>(&L);
}
__device__ __forceinline__ void sp1(float v, __nv_bfloat16* h, __nv_bfloat16* l) {
    __nv_bfloat16 hh = __float2bfloat16(v);
    *h = hh;
    *l = __float2bfloat16(v - __bfloat162float(hh));
}
__device__ __forceinline__ void ldsm4(uint32_t* r, uint32_t a) {
    asm volatile("ldmatrix.sync.aligned.m8n8.x4.shared.b16 {%0,%1,%2,%3}, [%4];"
                 : "=r"(r[0]), "=r"(r[1]), "=r"(r[2]), "=r"(r[3]) : "r"(a));
}
__device__ __forceinline__ void ldsm2(uint32_t* r, uint32_t a) {
    asm volatile("ldmatrix.sync.aligned.m8n8.x2.shared.b16 {%0,%1}, [%2];"
                 : "=r"(r[0]), "=r"(r[1]) : "r"(a));
}
__device__ __forceinline__ void ldsm4t(uint32_t* r, uint32_t a) {
    asm volatile("ldmatrix.sync.aligned.m8n8.x4.trans.shared.b16 {%0,%1,%2,%3}, [%4];"
                 : "=r"(r[0]), "=r"(r[1]), "=r"(r[2]), "=r"(r[3]) : "r"(a));
}
__device__ __forceinline__ void ldsm2t(uint32_t* r, uint32_t a) {
    asm volatile("ldmatrix.sync.aligned.m8n8.x2.trans.shared.b16 {%0,%1}, [%2];"
                 : "=r"(r[0]), "=r"(r[1]) : "r"(a));
}
__device__ __forceinline__ void mma_bf16(float* c, const uint32_t* a, const uint32_t* b) {
    asm volatile(
        "mma.sync.aligned.m16n8k16.row.col.f32.bf16.bf16.f32 "
        "{%0,%1,%2,%3}, {%4,%5,%6,%7}, {%8,%9}, {%0,%1,%2,%3};"
        : "+f"(c[0]), "+f"(c[1]), "+f"(c[2]), "+f"(c[3])
        : "r"(a[0]), "r"(a[1]), "r"(a[2]), "r"(a[3]), "r"(b[0]), "r"(b[1]));
}
// ---- cp.async ----
__device__ __forceinline__ void cpa16(uint32_t dst, const void* src) {
    asm volatile("cp.async.cg.shared.global [%0], [%1], 16;" :: "r"(dst), "l"(src));
}
__device__ __forceinline__ void cpa_commit() { asm volatile("cp.async.commit_group;"); }
template<int N> __device__ __forceinline__ void cpa_wait() {
    asm volatile("cp.async.wait_group %0;" :: "n"(N));
}
// nrows x 256B swizzled tile via cp.async (256 threads)
__device__ __forceinline__ void cp_tile256(uint32_t dst, const uint4* __restrict__ src,
                                           int nrows, int rs_u4, int tid) {
    int n = nrows * 16;
    for (int idx = tid; idx < n; idx += 256) {
        int r = idx >> 4, c8 = idx & 15;
        cpa16(dst + sw16(r, c8), src + r * rs_u4 + c8);
    }
}
// 128 rows x 64B swizzled tile (w2 chunk) via cp.async
__device__ __forceinline__ void cp_tile64B(uint32_t dst, const uint4* __restrict__ src,
                                           int rs_u4, int tid) {
#pragma unroll
    for (int i = 0; i < 2; ++i) {
        int idx = tid + i * 256;
        int r = idx >> 2, c8 = idx & 3;
        cpa16(dst + sw16_32(r, c8), src + r * rs_u4 + c8);
    }
}

// ===== warp tiling: 8 warps, 2m x 4n; each warp 32 rows x 32 cols (M=64 tile) =====

// xr[2][4][4]: C[64][128] += A(64x128k sw16) @ Bt(128n x 128k sw16)^T, 3-split
__device__ __forceinline__ void mma_att(float (&acc)[2][4][4],
                                        uint32_t aHi, uint32_t aLo,
                                        uint32_t bHi, uint32_t bLo,
                                        int warp_m, int warp_n, int lane) {
#pragma unroll
    for (int k8 = 0; k8 < 8; ++k8) {
        uint32_t aH[2][4], aL[2][4], bH[4][2], bL[4][2];
        int ar = warp_m * 32 + (lane & 15);
        int ac8 = k8 * 2 + (lane >> 4);
#pragma unroll
        for (int mi = 0; mi < 2; ++mi) {
            uint32_t off = sw16(ar + mi * 16, ac8);
            ldsm4(aH[mi], aHi + off);
            ldsm4(aL[mi], aLo + off);
        }
        int l15 = lane & 15;
        int br = warp_n * 32 + (l15 & 7);
        int bc8 = k8 * 2 + (l15 >> 3);
#pragma unroll
        for (int ni = 0; ni < 4; ++ni) {
            uint32_t off = sw16(br + ni * 8, bc8);
            ldsm2(bH[ni], bHi + off);
            ldsm2(bL[ni], bLo + off);
        }
#pragma unroll
        for (int mi = 0; mi < 2; ++mi)
#pragma unroll
            for (int ni = 0; ni < 4; ++ni) {
                mma_bf16(acc[mi][ni], aH[mi], bH[ni]);
                mma_bf16(acc[mi][ni], aH[mi], bL[ni]);
                mma_bf16(acc[mi][ni], aL[mi], bH[ni]);
            }
    }
}

// u[2][1][4]: U[64][32] = A(64x128k sw16) @ w1c(32n x 128k sw16)^T, 3-split
__device__ __forceinline__ void mma_w1(float (&u)[2][4],
                                       uint32_t aHi, uint32_t aLo,
                                       uint32_t bHi, uint32_t bLo,
                                       int warp_m, int warp_n, int lane) {
#pragma unroll
    for (int k8 = 0; k8 < 8; ++k8) {
        uint32_t aH[2][4], aL[2][4], bH[2], bL[2];
        int ar = warp_m * 32 + (lane & 15);
        int ac8 = k8 * 2 + (lane >> 4);
#pragma unroll
        for (int mi = 0; mi < 2; ++mi) {
            uint32_t off = sw16(ar + mi * 16, ac8);
            ldsm4(aH[mi], aHi + off);
            ldsm4(aL[mi], aLo + off);
        }
        int l15 = lane & 15;
        int br = warp_n * 8 + (l15 & 7);
        int bc8 = k8 * 2 + (l15 >> 3);
        uint32_t off = sw16(br, bc8);
        ldsm2(bH, bHi + off);
        ldsm2(bL, bLo + off);
#pragma unroll
        for (int mi = 0; mi < 2; ++mi) {
            mma_bf16(u[mi], aH[mi], bH);
            mma_bf16(u[mi], aH[mi], bL);
            mma_bf16(u[mi], aL[mi], bH);
        }
    }
}

// xr += F(64m x 32k sw_32) @ w2c(128n x 32k sw_32)^T, 3-split
__device__ __forceinline__ void mma_w2(float (&acc)[2][4][4],
                                       uint32_t fHi, uint32_t fLo,
                                       uint32_t bHi, uint32_t bLo,
                                       int warp_m, int warp_n, int lane) {
#pragma unroll
    for (int k8 = 0; k8 < 2; ++k8) {
        uint32_t aH[2][4], aL[2][4], bH[4][2], bL[4][2];
        int ar = warp_m * 32 + (lane & 15);
        int ac8 = k8 * 2 + (lane >> 4);
#pragma unroll
        for (int mi = 0; mi < 2; ++mi) {
            uint32_t off = sw16_32(ar + mi * 16, ac8);
            ldsm4(aH[mi], fHi + off);
            ldsm4(aL[mi], fLo + off);
        }
        int l15 = lane & 15;
        int br = warp_n * 32 + (l15 & 7);
        int bc8 = k8 * 2 + (l15 >> 3);
#pragma unroll
        for (int ni = 0; ni < 4; ++ni) {
            uint32_t off = sw16_32(br + ni * 8, bc8);
            ldsm2(bH[ni], bHi + off);
            ldsm2(bL[ni], bLo + off);
        }
#pragma unroll
        for (int mi = 0; mi < 2; ++mi)
#pragma unroll
            for (int ni = 0; ni < 4; ++ni) {
                mma_bf16(acc[mi][ni], aH[mi], bH[ni]);
                mma_bf16(acc[mi][ni], aH[mi], bL[ni]);
                mma_bf16(acc[mi][ni], aL[mi], bH[ni]);
            }
    }
}

// ga[4][4][4]: G[128][128] = H^T @ H over 64-row H tile (sw16), 3-split
__device__ __forceinline__ void mma_tt64(float (&acc)[4][4][4],
                                         uint32_t hHi, uint32_t hLo,
                                         int warp_m, int warp_n, int lane) {
#pragma unroll
    for (int k8 = 0; k8 < 4; ++k8) {
        int k0 = k8 * 16;
        uint32_t aH[4][4], aL[4][4], bH[4][2], bL[4][2];
        int ar = k0 + (lane & 7) + ((lane >> 4) << 3);
        int asel = (lane >> 3) & 1;
#pragma unroll
        for (int mi = 0; mi < 4; ++mi) {
            int c8 = ((warp_m * 64 + mi * 16) >> 3) + asel;
            uint32_t off = sw16(ar, c8);
            ldsm4t(aH[mi], hHi + off);
            ldsm4t(aL[mi], hLo + off);
        }
        int l15 = lane & 15;
        int br = k0 + (l15 & 7) + ((l15 >> 3) << 3);
#pragma unroll
        for (int ni = 0; ni < 4; ++ni) {
            int c8 = (warp_n * 32 + ni * 8) >> 3;
            uint32_t off = sw16(br, c8);
            ldsm2t(bH[ni], hHi + off);
            ldsm2t(bL[ni], hLo + off);
        }
#pragma unroll
        for (int mi = 0; mi < 4; ++mi)
#pragma unroll
            for (int ni = 0; ni < 4; ++ni) {
                mma_bf16(acc[mi][ni], aH[mi], bH[ni]);
                mma_bf16(acc[mi][ni], aH[mi], bL[ni]);
                mma_bf16(acc[mi][ni], aL[mi], bH[ni]);
            }
    }
}

// LayerNorm of 64-row fragment-layout values -> split hi/lo into sw16 tile.
__device__ __forceinline__ void ln64(const float (&v)[2][4][4],
                                     const float* gs, const float* bs,
                                     char* Ahi, char* Alo,
                                     float2* red, float2* mrs,
                                     int warp_m, int warp_n, int lane, int tid) {
    int row0 = warp_m * 32 + (lane >> 2);
    int col0 = warp_n * 32 + (lane & 3) * 2;
#pragma unroll
    for (int mi = 0; mi < 2; ++mi) {
        float s1 = 0, q1 = 0, s2 = 0, q2 = 0;
#pragma unroll
        for (int ni = 0; ni < 4; ++ni) {
            s1 += v[mi][ni][0] + v[mi][ni][1];
            q1 += v[mi][ni][0] * v[mi][ni][0] + v[mi][ni][1] * v[mi][ni][1];
            s2 += v[mi][ni][2] + v[mi][ni][3];
            q2 += v[mi][ni][2] * v[mi][ni][2] + v[mi][ni][3] * v[mi][ni][3];
        }
        s1 += __shfl_xor_sync(~0u, s1, 1); s1 += __shfl_xor_sync(~0u, s1, 2);
        q1 += __shfl_xor_sync(~0u, q1, 1); q1 += __shfl_xor_sync(~0u, q1, 2);
        s2 += __shfl_xor_sync(~0u, s2, 1); s2 += __shfl_xor_sync(~0u, s2, 2);
        q2 += __shfl_xor_sync(~0u, q2, 1); q2 += __shfl_xor_sync(~0u, q2, 2);
        if ((lane & 3) == 0) {
            int r1 = row0 + mi * 16;
            red[r1 * 4 + warp_n] = make_float2(s1, q1);
            red[(r1 + 8) * 4 + warp_n] = make_float2(s2, q2);
        }
    }
    __syncthreads();
    if (tid < 64) {
        float s = 0, q = 0;
#pragma unroll
        for (int w = 0; w < 4; ++w) { float2 p = red[tid * 4 + w]; s += p.x; q += p.y; }
        float m = s * (1.0f / 128.0f);
        float var = q * (1.0f / 128.0f) - m * m;
        mrs[tid] = make_float2(m, rsqrtf(var + EPSm));
    }
    __syncthreads();
#pragma unroll
    for (int mi = 0; mi < 2; ++mi) {
        float2 m1 = mrs[row0 + mi * 16];
        float2 m2 = mrs[row0 + mi * 16 + 8];
#pragma unroll
        for (int ni = 0; ni < 4; ++ni) {
            int col = col0 + ni * 8;
            float g0 = gs[col], g1 = gs[col + 1], bb0 = bs[col], bb1 = bs[col + 1];
            int r1 = row0 + mi * 16, r2 = r1 + 8;
            float f0 = (v[mi][ni][0] - m1.x) * m1.y * g0 + bb0;
            float f1 = (v[mi][ni][1] - m1.x) * m1.y * g1 + bb1;
            float f2 = (v[mi][ni][2] - m2.x) * m2.y * g0 + bb0;
            float f3 = (v[mi][ni][3] - m2.x) * m2.y * g1 + bb1;
            uint32_t h, l;
            uint32_t o1 = sw4(r1, col), o2 = sw4(r2, col);
            split2(f0, f1, h, l);
            *reinterpret_cast<uint32_t*>(Ahi + o1) = h;
            *reinterpret_cast<uint32_t*>(Alo + o1) = l;
            split2(f2, f3, h, l);
            *reinterpret_cast<uint32_t*>(Ahi + o2) = h;
            *reinterpret_cast<uint32_t*>(Alo + o2) = l;
        }
    }
    __syncthreads();
}

// ============================ kernels ============================

__global__ void kprep_kernel(const float* __restrict__ w1, const float* __restrict__ w2,
                             const float* __restrict__ outw) {
    int idx = blockIdx.x * 256 + threadIdx.x;
    if (idx < 65536) {                 // w1t [512 n][128 k]
        int n = idx >> 7, k = idx & 127;
        sp1(w1[k * 512 + n], &g_w1t_hi[idx], &g_w1t_lo[idx]);
    } else if (idx < 131072) {         // w2t [128 n][512 k]
        int j = idx - 65536;
        int n = j >> 9, k = j & 511;
        sp1(w2[k * 128 + n], &g_w2t_hi[j], &g_w2t_lo[j]);
    } else if (idx < 147456) {         // owt [128 n][128 k]
        int j = idx - 131072;
        int n = j >> 7, k = j & 127;
        sp1(outw[k * 128 + n], &g_owt_hi[j], &g_owt_lo[j]);
    }
}

// t=0 Gram partials: one 64-row tile per CTA; h = LN1(x); part = h^T h.
#define KG_H    3584
#define KG_SMEM (KG_H + 32768)   // 36352
__global__ void __launch_bounds__(256, 2)
kgram0(const float* __restrict__ xin,
       const float* __restrict__ lng, const float* __restrict__ lnb) {
    extern __shared__ char sm[];
    float* gs = reinterpret_cast<float*>(sm);            // 512
    float* bs = gs + 128;                                // 512
    float2* red = reinterpret_cast<float2*>(sm + 1024);  // 2048
    float2* mrs = reinterpret_cast<float2*>(sm + 3072);  // 512
    char* Hhi = sm + KG_H;
    char* Hlo = sm + KG_H + 16384;
    uint32_t smb = smem_u32(sm);
    int tid = threadIdx.x, lane = tid & 31, wid = tid >> 5;
    int warp_m = wid & 1, warp_n = wid >> 1;
    int row0 = warp_m * 32 + (lane >> 2);
    int col0 = warp_n * 32 + (lane & 3) * 2;
    if (tid < 128) { gs[tid] = lng[tid]; bs[tid] = lnb[tid]; }
    __syncthreads();

    const float* xt = xin + (size_t)blockIdx.x * 8192;
    float v[2][4][4];
#pragma unroll
    for (int mi = 0; mi < 2; ++mi)
#pragma unroll
        for (int ni = 0; ni < 4; ++ni) {
            const float* p = xt + (row0 + mi * 16) * 128 + col0 + ni * 8;
            float2 a = *reinterpret_cast<const float2*>(p);
            float2 b = *reinterpret_cast<const float2*>(p + 8 * 128);
            v[mi][ni][0] = a.x; v[mi][ni][1] = a.y;
            v[mi][ni][2] = b.x; v[mi][ni][3] = b.y;
        }
    ln64(v, gs, bs, Hhi, Hlo, red, mrs, warp_m, warp_n, lane, tid);

    float ga[4][4][4];
#pragma unroll
    for (int mi = 0; mi < 4; ++mi)
#pragma unroll
        for (int ni = 0; ni < 4; ++ni)
#pragma unroll
            for (int e = 0; e < 4; ++e) ga[mi][ni][e] = 0.f;
    mma_tt64(ga, smb + KG_H, smb + KG_H + 16384, warp_m, warp_n, lane);

    float* dst = g_part + (size_t)blockIdx.x * 16384;
#pragma unroll
    for (int mi = 0; mi < 4; ++mi)
#pragma unroll
        for (int ni = 0; ni < 4; ++ni) {
            int r1 = (warp_m * 64 + mi * 16) + (lane >> 2), col = col0 + ni * 8;
            *reinterpret_cast<float2*>(dst + r1 * 128 + col) =
                make_float2(ga[mi][ni][0], ga[mi][ni][1]);
            *reinterpret_cast<float2*>(dst + (r1 + 8) * 128 + col) =
                make_float2(ga[mi][ni][2], ga[mi][ni][3]);
        }
}

// stage-1 reduce: 2048 partials -> 64 partials. 1M threads, 32 loads each.
__global__ void kred1_kernel() {
    int idx = blockIdx.x * 256 + threadIdx.x;
    int e = idx & 16383;
    int g = idx >> 14;
    const float* p = g_part + (size_t)g * 32 * 16384 + e;
    float s = 0.f;
#pragma unroll
    for (int i = 0; i < 32; ++i) s += p[(size_t)i * 16384];
    g_part2[(size_t)g * 16384 + e] = s;
}

// Small 128^3 GEMMs (op1 fuses stage-2 reduce of g_part2).
#define TS_SMEM (128 * 129 * 4 + 512 * 4)
__global__ void __launch_bounds__(256, 1)
ktiny3(const float* __restrict__ A, const float* __restrict__ B, int op) {
    extern __shared__ float ts[];
    float* Bs = ts;
    float* As = ts + 128 * 129;
    int tid = threadIdx.x;
    const float* Bp = (op == 2) ? g_T1 : B;
    for (int idx = tid; idx < 16384; idx += 256)
        Bs[(idx >> 7) * 129 + (idx & 127)] = Bp[idx];
    int r0 = blockIdx.x * 4;
    if (op == 1) {
        for (int idx = tid; idx < 512; idx += 256) {
            int off = (r0 + (idx >> 7)) * 128 + (idx & 127);
            const float* p = g_part2 + off;
            float s = 0.f;
#pragma unroll 8
            for (int g = 0; g < 64; ++g) s += p[(size_t)g * 16384];
            As[idx] = s;
        }
    } else {
        const float* Ap = (op == 0) ? A : g_QK;
        for (int idx = tid; idx < 512; idx += 256)
            As[idx] = Ap[(r0 + (idx >> 7)) * 128 + (idx & 127)];
    }
    __syncthreads();
    int j = tid & 127, i0 = (tid >> 7) * 2;
    float c0 = 0.f, c1 = 0.f;
    if (op == 0) {
#pragma unroll 8
        for (int k = 0; k < 128; ++k) {
            float b = Bs[j * 129 + k];
            c0 = fmaf(As[i0 * 128 + k], b, c0);
            c1 = fmaf(As[i0 * 128 + 128 + k], b, c1);
        }
    } else {
#pragma unroll 8
        for (int k = 0; k < 128; ++k) {
            float b = Bs[k * 129 + j];
            c0 = fmaf(As[i0 * 128 + k], b, c0);
            c1 = fmaf(As[i0 * 128 + 128 + k], b, c1);
        }
    }
    if (op == 2) {
        sp1(c0, &g_Mt_hi[j * 128 + r0 + i0], &g_Mt_lo[j * 128 + r0 + i0]);
        sp1(c1, &g_Mt_hi[j * 128 + r0 + i0 + 1], &g_Mt_lo[j * 128 + r0 + i0 + 1]);
    } else {
        float* C = (op == 0) ? g_QK : g_T1;
        C[(r0 + i0) * 128 + j] = c0;
        C[(r0 + i0 + 1) * 128 + j] = c1;
    }
}

// ========= big fused kernel: 64-row tiles, occ 2, cp.async pipeline =========
#define KC_RED  5120
#define KC_MRS  7168
#define KC_A    7680                   // Ahi 16K | Alo 16K  -> 40448
#define KC_B0   40448                  // 16K (attn: Mt-hi spans B0+B1)
#define KC_B1   56832                  // 16K
#define KC_F    73216                  // Fhi 4K | Flo 4K
#define KC_W    81408                  // 32K (attn Mt-lo / out-proj)
#define KC_SMEM 114176

__global__ void __launch_bounds__(256, 2)
kc_mma(const float* __restrict__ xin, int srcIsG,
       const float* __restrict__ ln1g, const float* __restrict__ ln1b,
       const float* __restrict__ ln2g, const float* __restrict__ ln2b,
       const float* __restrict__ b1, const float* __restrict__ b2,
       const float* __restrict__ outb, float* __restrict__ outp, int last) {
    extern __shared__ char sm[];
    uint32_t smb = smem_u32(sm);
    int tid = threadIdx.x, lane = tid & 31, wid = tid >> 5;
    int warp_m = wid & 1, warp_n = wid >> 1;
    int row0 = warp_m * 32 + (lane >> 2);
    int col0 = warp_n * 32 + (lane & 3) * 2;

    float* ln1gs = reinterpret_cast<float*>(sm);
    float* ln1bs = ln1gs + 128;
    float* ln2gs = ln1gs + 256;
    float* ln2bs = ln1gs + 384;
    float* b2s   = ln1gs + 512;
    float* outbs = ln1gs + 640;
    float* b1s   = ln1gs + 768;     // 512 floats
    float2* red  = reinterpret_cast<float2*>(sm + KC_RED);
    float2* mrs  = reinterpret_cast<float2*>(sm + KC_MRS);
    if (tid < 128) {
        ln1gs[tid] = ln1g[tid]; ln1bs[tid] = ln1b[tid];
        ln2gs[tid] = ln2g[tid]; ln2bs[tid] = ln2b[tid];
        b2s[tid] = b2[tid]; outbs[tid] = outb[tid];
    }
    b1s[tid] = b1[tid]; b1s[tid + 256] = b1[tid + 256];

    // prefetch Mt: hi -> B0span (32KB contiguous), lo -> W
    cp_tile256(smb + KC_B0, reinterpret_cast<const uint4*>(g_Mt_hi), 128, 16, tid);
    cp_tile256(smb + KC_W,  reinterpret_cast<const uint4*>(g_Mt_lo), 128, 16, tid);
    cpa_commit();

    // x tile (64 rows) in fragment layout
    size_t base = (size_t)blockIdx.x * 8192;
    const float* xt = (srcIsG ? g_x : xin) + base;
    float xr[2][4][4];
#pragma unroll
    for (int mi = 0; mi < 2; ++mi)
#pragma unroll
        for (int ni = 0; ni < 4; ++ni) {
            const float* p = xt + (row0 + mi * 16) * 128 + col0 + ni * 8;
            float2 a = *reinterpret_cast<const float2*>(p);
            float2 b = *reinterpret_cast<const float2*>(p + 8 * 128);
            xr[mi][ni][0] = a.x; xr[mi][ni][1] = a.y;
            xr[mi][ni][2] = b.x; xr[mi][ni][3] = b.y;
        }

    // A <- LN1(x)
    ln64(xr, ln1gs, ln1bs, sm + KC_A, sm + KC_A + 16384, red, mrs, warp_m, warp_n, lane, tid);
    cpa_wait<0>();
    __syncthreads();
    // x += h @ M
    mma_att(xr, smb + KC_A, smb + KC_A + 16384, smb + KC_B0, smb + KC_W, warp_m, warp_n, lane);
    __syncthreads();

    // prime FF: w1 chunk 0 -> B0
    cp_tile256(smb + KC_B0,        reinterpret_cast<const uint4*>(g_w1t_hi), 32, 16, tid);
    cp_tile256(smb + KC_B0 + 8192, reinterpret_cast<const uint4*>(g_w1t_lo), 32, 16, tid);
    cpa_commit();

    // A <- LN2(x)
    ln64(xr, ln2gs, ln2bs, sm + KC_A, sm + KC_A + 16384, red, mrs, warp_m, warp_n, lane, tid);

    // FF: 16 chunks of 32 hidden units, double-buffered weights
#pragma unroll 1
    for (int c = 0; c < 16; ++c) {
        // prefetch w2_c -> B1
        cp_tile64B(smb + KC_B1,        reinterpret_cast<const uint4*>(g_w2t_hi) + c * 4, 64, tid);
        cp_tile64B(smb + KC_B1 + 8192, reinterpret_cast<const uint4*>(g_w2t_lo) + c * 4, 64, tid);
        cpa_commit();
        cpa_wait<1>();           // w1_c ready in B0
        __syncthreads();
        float u[2][4];
#pragma unroll
        for (int mi = 0; mi < 2; ++mi)
#pragma unroll
            for (int e = 0; e < 4; ++e) u[mi][e] = 0.f;
        mma_w1(u, smb + KC_A, smb + KC_A + 16384, smb + KC_B0, smb + KC_B0 + 8192,
               warp_m, warp_n, lane);
        // bias + relu + split -> F (64B-row swizzle)
        {
            int hcol = warp_n * 8 + (lane & 3) * 2;            // 0..31
            float bb0 = b1s[c * 32 + hcol], bb1 = b1s[c * 32 + hcol + 1];
#pragma unroll
            for (int mi = 0; mi < 2; ++mi) {
                int r1 = row0 + mi * 16, r2 = r1 + 8;
                float f0 = fmaxf(u[mi][0] + bb0, 0.f);
                float f1 = fmaxf(u[mi][1] + bb1, 0.f);
                float f2 = fmaxf(u[mi][2] + bb0, 0.f);
                float f3 = fmaxf(u[mi][3] + bb1, 0.f);
                uint32_t h, l;
                uint32_t o1 = sw4_32(r1, hcol), o2 = sw4_32(r2, hcol);
                split2(f0, f1, h, l);
                *reinterpret_cast<uint32_t*>(sm + KC_F + o1) = h;
                *reinterpret_cast<uint32_t*>(sm + KC_F + 4096 + o1) = l;
                split2(f2, f3, h, l);
                *reinterpret_cast<uint32_t*>(sm + KC_F + o2) = h;
                *reinterpret_cast<uint32_t*>(sm + KC_F + 4096 + o2) = l;
            }
        }
        __syncthreads();         // F visible; B0 (w1_c) free
        if (c < 15) {
            cp_tile256(smb + KC_B0,        reinterpret_cast<const uint4*>(g_w1t_hi) + (c + 1) * 512, 32, 16, tid);
            cp_tile256(smb + KC_B0 + 8192, reinterpret_cast<const uint4*>(g_w1t_lo) + (c + 1) * 512, 32, 16, tid);
        }
        cpa_commit();            // (empty group OK on c==15)
        cpa_wait<1>();           // w2_c ready in B1
        __syncthreads();
        mma_w2(xr, smb + KC_F, smb + KC_F + 4096, smb + KC_B1, smb + KC_B1 + 8192,
               warp_m, warp_n, lane);
        __syncthreads();         // B1/F free for next chunk
    }

    // + b2
#pragma unroll
    for (int mi = 0; mi < 2; ++mi)
#pragma unroll
        for (int ni = 0; ni < 4; ++ni) {
            int col = col0 + ni * 8;
            xr[mi][ni][0] += b2s[col];     xr[mi][ni][1] += b2s[col + 1];
            xr[mi][ni][2] += b2s[col];     xr[mi][ni][3] += b2s[col + 1];
        }

    if (!last) {
        // store x_new
        float* dst = g_x + base;
#pragma unroll
        for (int mi = 0; mi < 2; ++mi)
#pragma unroll
            for (int ni = 0; ni < 4; ++ni) {
                int r1 = row0 + mi * 16, col = col0 + ni * 8;
                *reinterpret_cast<float2*>(dst + r1 * 128 + col) =
                    make_float2(xr[mi][ni][0], xr[mi][ni][1]);
                *reinterpret_cast<float2*>(dst + (r1 + 8) * 128 + col) =
                    make_float2(xr[mi][ni][2], xr[mi][ni][3]);
            }
        // fused Gram partial for NEXT step: h = LN1(x_new); part = h^T h
        ln64(xr, ln1gs, ln1bs, sm + KC_A, sm + KC_A + 16384, red, mrs, warp_m, warp_n, lane, tid);
        float ga[4][4][4];
#pragma unroll
        for (int mi = 0; mi < 4; ++mi)
#pragma unroll
            for (int ni = 0; ni < 4; ++ni)
#pragma unroll
                for (int e = 0; e < 4; ++e) ga[mi][ni][e] = 0.f;
        mma_tt64(ga, smb + KC_A, smb + KC_A + 16384, warp_m, warp_n, lane);
        float* pdst = g_part + (size_t)blockIdx.x * 16384;
#pragma unroll
        for (int mi = 0; mi < 4; ++mi)
#pragma unroll
            for (int ni = 0; ni < 4; ++ni) {
                int r1 = (warp_m * 64 + mi * 16) + (lane >> 2), col = col0 + ni * 8;
                *reinterpret_cast<float2*>(pdst + r1 * 128 + col) =
                    make_float2(ga[mi][ni][0], ga[mi][ni][1]);
                *reinterpret_cast<float2*>(pdst + (r1 + 8) * 128 + col) =
                    make_float2(ga[mi][ni][2], ga[mi][ni][3]);
            }
    } else {
        // out = x @ outw + outb: owt hi -> W, lo -> B0span
        cp_tile256(smb + KC_W,  reinterpret_cast<const uint4*>(g_owt_hi), 128, 16, tid);
        cp_tile256(smb + KC_B0, reinterpret_cast<const uint4*>(g_owt_lo), 128, 16, tid);
        cpa_commit();
        // split x -> A
#pragma unroll
        for (int mi = 0; mi < 2; ++mi)
#pragma unroll
            for (int ni = 0; ni < 4; ++ni) {
                int col = col0 + ni * 8;
                int r1 = row0 + mi * 16, r2 = r1 + 8;
                uint32_t h, l;
                uint32_t o1 = sw4(r1, col), o2 = sw4(r2, col);
                split2(xr[mi][ni][0], xr[mi][ni][1], h, l);
                *reinterpret_cast<uint32_t*>(sm + KC_A + o1) = h;
                *reinterpret_cast<uint32_t*>(sm + KC_A + 16384 + o1) = l;
                split2(xr[mi][ni][2], xr[mi][ni][3], h, l);
                *reinterpret_cast<uint32_t*>(sm + KC_A + o2) = h;
                *reinterpret_cast<uint32_t*>(sm + KC_A + 16384 + o2) = l;
            }
        cpa_wait<0>();
        __syncthreads();
        float o[2][4][4];
#pragma unroll
        for (int mi = 0; mi < 2; ++mi)
#pragma unroll
            for (int ni = 0; ni < 4; ++ni)
#pragma unroll
                for (int e = 0; e < 4; ++e) o[mi][ni][e] = 0.f;
        mma_att(o, smb + KC_A, smb + KC_A + 16384, smb + KC_W, smb + KC_B0, warp_m, warp_n, lane);
        float* dst = outp + base;
#pragma unroll
        for (int mi = 0; mi < 2; ++mi)
#pragma unroll
            for (int ni = 0; ni < 4; ++ni) {
                int r1 = row0 + mi * 16, col = col0 + ni * 8;
                *reinterpret_cast<float2*>(dst + r1 * 128 + col) =
                    make_float2(o[mi][ni][0] + outbs[col], o[mi][ni][1] + outbs[col + 1]);
                *reinterpret_cast<float2*>(dst + (r1 + 8) * 128 + col) =
                    make_float2(o[mi][ni][2] + outbs[col], o[mi][ni][3] + outbs[col + 1]);
            }
    }
}

// ============================ host launcher ============================
extern "C" void kernel_launch(void* const* d_in, const int* in_sizes, int n_in,
                              void* d_out, int out_size) {
    (void)in_sizes; (void)n_in; (void)out_size;
    const float* x    = (const float*)d_in[0];
    const float* Kw   = (const float*)d_in[1];
    const float* Qw   = (const float*)d_in[2];
    const float* Vw   = (const float*)d_in[3];
    const float* ln1g = (const float*)d_in[4];
    const float* ln1b = (const float*)d_in[5];
    const float* ln2g = (const float*)d_in[6];
    const float* ln2b = (const float*)d_in[7];
    const float* w1   = (const float*)d_in[8];
    const float* b1   = (const float*)d_in[9];
    const float* w2   = (const float*)d_in[10];
    const float* b2   = (const float*)d_in[11];
    const float* outw = (const float*)d_in[12];
    const float* outb = (const float*)d_in[13];
    float* out = (float*)d_out;

    cudaFuncSetAttribute(kc_mma, cudaFuncAttributeMaxDynamicSharedMemorySize, KC_SMEM);
    cudaFuncSetAttribute(kgram0, cudaFuncAttributeMaxDynamicSharedMemorySize, KG_SMEM);
    cudaFuncSetAttribute(ktiny3, cudaFuncAttributeMaxDynamicSharedMemorySize, TS_SMEM);

    kprep_kernel<<<576, 256>>>(w1, w2, outw);
    ktiny3<<<32, 256, TS_SMEM>>>(Qw, Kw, 0);            // QK = Qw @ Kw^T
    kgram0<<<NTILESm, 256, KG_SMEM>>>(x, ln1g, ln1b);

    for (int t = 0; t < 4; ++t) {
        int srcIsG = (t != 0);
        kred1_kernel<<<4096, 256>>>();                        // 2048 -> 64 partials
        ktiny3<<<32, 256, TS_SMEM>>>(nullptr, Vw, 1);         // T1 = G @ Vw (+ stage-2 reduce)
        ktiny3<<<32, 256, TS_SMEM>>>(nullptr, nullptr, 2);    // Mt = QK @ T1 (split)
        kc_mma<<<NTILESm, 256, KC_SMEM>>>(x, srcIsG, ln1g, ln1b, ln2g, ln2b,
                                          b1, b2, outb, out, t == 3);
    }
}

// round 10
// speedup vs baseline: 1.2727x; 1.2727x over previous
#include <cuda_runtime.h>
#include <cuda_bf16.h>
#include <cstdint>

#define EPSm   1e-5f
#define NROWSm 131072
#define NTILESm 1024
#define NPART  1024

// ---------------- device scratch ----------------
__device__ float g_x[NROWSm * 128];
__device__ float g_part[NPART * 128 * 128];   // 64 MB gram partials (stage 0)
__device__ float g_part2[64 * 128 * 128];     // 4 MB  (stage 1)
__device__ float g_QK[128 * 128];
__device__ float g_T1[128 * 128];
__device__ unsigned g_barrier;                // monotonic ticket barrier for kmid
__device__ __nv_bfloat16 g_Mt_hi[128 * 128],  g_Mt_lo[128 * 128];
__device__ __nv_bfloat16 g_w1t_hi[512 * 128], g_w1t_lo[512 * 128];   // [512 n][128 k]
__device__ __nv_bfloat16 g_w2t_hi[128 * 512], g_w2t_lo[128 * 512];   // [128 n][512 k]
__device__ __nv_bfloat16 g_owt_hi[128 * 128], g_owt_lo[128 * 128];

// ---------------- helpers ----------------
__device__ __forceinline__ uint32_t smem_u32(const void* p) {
    uint32_t a;
    asm("{ .reg .u64 t; cvta.to.shared.u64 t, %1; cvt.u32.u64 %0, t; }" : "=r"(a) : "l"(p));
    return a;
}
// XOR-swizzled tile, 256B rows (128 bf16 cols)
__device__ __forceinline__ uint32_t sw16(int r, int c8) {
    return (uint32_t)(r * 256 + ((c8 ^ (r & 7)) << 4));
}
__device__ __forceinline__ uint32_t sw4(int r, int col) {
    return (uint32_t)(r * 256 + ((((col >> 3) ^ (r & 7)) << 4)) + (col & 7) * 2);
}
// XOR-swizzled tile, 128B rows (64 bf16 cols)
__device__ __forceinline__ uint32_t sw16_64(int r, int c8) {
    return (uint32_t)(r * 128 + ((((c8 ^ (r & 7)) & 7) << 4)));
}
__device__ __forceinline__ uint32_t sw4_64(int r, int col) {
    return (uint32_t)(r * 128 + ((((col >> 3) ^ (r & 7)) & 7) << 4) + (col & 7) * 2);
}
__device__ __forceinline__ void split2(float f0, float f1, uint32_t& hi, uint32_t& lo) {
    __nv_bfloat162 H = __floats2bfloat162_rn(f0, f1);
    float r0 = f0 - __bfloat162float(H.x);
    float r1 = f1 - __bfloat162float(H.y);
    __nv_bfloat162 L = __floats2bfloat162_rn(r0, r1);
    hi = *reinterpret_cast<uint32_t*>(&H);
    lo = *reinterpret_cast<uint32_t*>(&L);
}
__device__ __forceinline__ void sp1(float v, __nv_bfloat16* h, __nv_bfloat16* l) {
    __nv_bfloat16 hh = __float2bfloat16(v);
    *h = hh;
    *l = __float2bfloat16(v - __bfloat162float(hh));
}
__device__ __forceinline__ void ldsm4(uint32_t* r, uint32_t a) {
    asm volatile("ldmatrix.sync.aligned.m8n8.x4.shared.b16 {%0,%1,%2,%3}, [%4];"
                 : "=r"(r[0]), "=r"(r[1]), "=r"(r[2]), "=r"(r[3]) : "r"(a));
}
__device__ __forceinline__ void ldsm2(uint32_t* r, uint32_t a) {
    asm volatile("ldmatrix.sync.aligned.m8n8.x2.shared.b16 {%0,%1}, [%2];"
                 : "=r"(r[0]), "=r"(r[1]) : "r"(a));
}
__device__ __forceinline__ void ldsm4t(uint32_t* r, uint32_t a) {
    asm volatile("ldmatrix.sync.aligned.m8n8.x4.trans.shared.b16 {%0,%1,%2,%3}, [%4];"
                 : "=r"(r[0]), "=r"(r[1]), "=r"(r[2]), "=r"(r[3]) : "r"(a));
}
__device__ __forceinline__ void ldsm2t(uint32_t* r, uint32_t a) {
    asm volatile("ldmatrix.sync.aligned.m8n8.x2.trans.shared.b16 {%0,%1}, [%2];"
                 : "=r"(r[0]), "=r"(r[1]) : "r"(a));
}
__device__ __forceinline__ void mma_bf16(float* c, const uint32_t* a, const uint32_t* b) {
    asm volatile(
        "mma.sync.aligned.m16n8k16.row.col.f32.bf16.bf16.f32 "
        "{%0,%1,%2,%3}, {%4,%5,%6,%7}, {%8,%9}, {%0,%1,%2,%3};"
        : "+f"(c[0]), "+f"(c[1]), "+f"(c[2]), "+f"(c[3])
        : "r"(a[0]), "r"(a[1]), "r"(a[2]), "r"(a[3]), "r"(b[0]), "r"(b[1]));
}
// ---- cp.async ----
__device__ __forceinline__ void cpa16(uint32_t dst, const void* src) {
    asm volatile("cp.async.cg.shared.global [%0], [%1], 16;" :: "r"(dst), "l"(src));
}
__device__ __forceinline__ void cpa_commit() { asm volatile("cp.async.commit_group;"); }
template<int N> __device__ __forceinline__ void cpa_wait() {
    asm volatile("cp.async.wait_group %0;" :: "n"(N));
}
// nrows x 256B swizzled tile via cp.async (256 threads)
__device__ __forceinline__ void cp_tile256(uint32_t dst, const uint4* __restrict__ src,
                                           int nrows, int rs_u4, int tid) {
    int n = nrows * 16;
    for (int idx = tid; idx < n; idx += 256) {
        int r = idx >> 4, c8 = idx & 15;
        cpa16(dst + sw16(r, c8), src + r * rs_u4 + c8);
    }
}
// 128 rows x 128B swizzled tile via cp.async
__device__ __forceinline__ void cp_tile128(uint32_t dst, const uint4* __restrict__ src,
                                           int rs_u4, int tid) {
#pragma unroll
    for (int i = 0; i < 4; ++i) {
        int idx = tid + i * 256;
        int r = idx >> 3, c8 = idx & 7;
        cpa16(dst + sw16_64(r, c8), src + r * rs_u4 + c8);
    }
}

// C[128][128] += A(128x128k) @ Bt(128n x 128k)^T, bf16 3-split (256B-row tiles)
__device__ __forceinline__ void mma_nt(float (&acc)[4][4][4],
                                       uint32_t aHi, uint32_t aLo,
                                       uint32_t bHi, uint32_t bLo,
                                       int warp_m, int warp_n, int lane) {
#pragma unroll
    for (int k8 = 0; k8 < 8; ++k8) {
        uint32_t aH[4][4], aL[4][4], bH[4][2], bL[4][2];
        int ar = warp_m * 64 + (lane & 15);
        int ac8 = k8 * 2 + (lane >> 4);
#pragma unroll
        for (int mi = 0; mi < 4; ++mi) {
            uint32_t off = sw16(ar + mi * 16, ac8);
            ldsm4(aH[mi], aHi + off);
            ldsm4(aL[mi], aLo + off);
        }
        int l15 = lane & 15;
        int br = warp_n * 32 + (l15 & 7);
        int bc8 = k8 * 2 + (l15 >> 3);
#pragma unroll
        for (int ni = 0; ni < 4; ++ni) {
            uint32_t off = sw16(br + ni * 8, bc8);
            ldsm2(bH[ni], bHi + off);
            ldsm2(bL[ni], bLo + off);
        }
#pragma unroll
        for (int mi = 0; mi < 4; ++mi)
#pragma unroll
            for (int ni = 0; ni < 4; ++ni) {
                mma_bf16(acc[mi][ni], aH[mi], bH[ni]);
                mma_bf16(acc[mi][ni], aH[mi], bL[ni]);
                mma_bf16(acc[mi][ni], aL[mi], bH[ni]);
            }
    }
}

// u[128][64] = A(128x128k) @ Bt(64n x 128k)^T  (B tile 64 rows, 256B rows)
__device__ __forceinline__ void mma_n64(float (&u)[4][2][4],
                                        uint32_t aHi, uint32_t aLo,
                                        uint32_t bHi, uint32_t bLo,
                                        int warp_m, int warp_n, int lane) {
#pragma unroll
    for (int k8 = 0; k8 < 8; ++k8) {
        uint32_t aH[4][4], aL[4][4], bH[2][2], bL[2][2];
        int ar = warp_m * 64 + (lane & 15);
        int ac8 = k8 * 2 + (lane >> 4);
#pragma unroll
        for (int mi = 0; mi < 4; ++mi) {
            uint32_t off = sw16(ar + mi * 16, ac8);
            ldsm4(aH[mi], aHi + off);
            ldsm4(aL[mi], aLo + off);
        }
        int l15 = lane & 15;
        int br = warp_n * 16 + (l15 & 7);
        int bc8 = k8 * 2 + (l15 >> 3);
#pragma unroll
        for (int ni = 0; ni < 2; ++ni) {
            uint32_t off = sw16(br + ni * 8, bc8);
            ldsm2(bH[ni], bHi + off);
            ldsm2(bL[ni], bLo + off);
        }
#pragma unroll
        for (int mi = 0; mi < 4; ++mi)
#pragma unroll
            for (int ni = 0; ni < 2; ++ni) {
                mma_bf16(u[mi][ni], aH[mi], bH[ni]);
                mma_bf16(u[mi][ni], aH[mi], bL[ni]);
                mma_bf16(u[mi][ni], aL[mi], bH[ni]);
            }
    }
}

// C[128][128] += F(128m x 64k) @ Bt(128n x 64k)^T  (128B-row tiles)
__device__ __forceinline__ void mma_k64(float (&acc)[4][4][4],
                                        uint32_t fHi, uint32_t fLo,
                                        uint32_t bHi, uint32_t bLo,
                                        int warp_m, int warp_n, int lane) {
#pragma unroll
    for (int k8 = 0; k8 < 4; ++k8) {
        uint32_t aH[4][4], aL[4][4], bH[4][2], bL[4][2];
        int ar = warp_m * 64 + (lane & 15);
        int ac8 = k8 * 2 + (lane >> 4);
#pragma unroll
        for (int mi = 0; mi < 4; ++mi) {
            uint32_t off = sw16_64(ar + mi * 16, ac8);
            ldsm4(aH[mi], fHi + off);
            ldsm4(aL[mi], fLo + off);
        }
        int l15 = lane & 15;
        int br = warp_n * 32 + (l15 & 7);
        int bc8 = k8 * 2 + (l15 >> 3);
#pragma unroll
        for (int ni = 0; ni < 4; ++ni) {
            uint32_t off = sw16_64(br + ni * 8, bc8);
            ldsm2(bH[ni], bHi + off);
            ldsm2(bL[ni], bLo + off);
        }
#pragma unroll
        for (int mi = 0; mi < 4; ++mi)
#pragma unroll
            for (int ni = 0; ni < 4; ++ni) {
                mma_bf16(acc[mi][ni], aH[mi], bH[ni]);
                mma_bf16(acc[mi][ni], aH[mi], bL[ni]);
                mma_bf16(acc[mi][ni], aL[mi], bH[ni]);
            }
    }
}

// Gram: C += H^T @ H, bf16 3-split; trans loads of row-major H tile.
__device__ __forceinline__ void mma_tt(float (&acc)[4][4][4],
                                       uint32_t hHi, uint32_t hLo,
                                       int warp_m, int warp_n, int lane) {
#pragma unroll
    for (int k8 = 0; k8 < 8; ++k8) {
        int k0 = k8 * 16;
        uint32_t aH[4][4], aL[4][4], bH[4][2], bL[4][2];
        int ar = k0 + (lane & 7) + ((lane >> 4) << 3);
        int asel = (lane >> 3) & 1;
#pragma unroll
        for (int mi = 0; mi < 4; ++mi) {
            int c8 = ((warp_m * 64 + mi * 16) >> 3) + asel;
            uint32_t off = sw16(ar, c8);
            ldsm4t(aH[mi], hHi + off);
            ldsm4t(aL[mi], hLo + off);
        }
        int l15 = lane & 15;
        int br = k0 + (l15 & 7) + ((l15 >> 3) << 3);
#pragma unroll
        for (int ni = 0; ni < 4; ++ni) {
            int c8 = (warp_n * 32 + ni * 8) >> 3;
            uint32_t off = sw16(br, c8);
            ldsm2t(bH[ni], hHi + off);
            ldsm2t(bL[ni], hLo + off);
        }
#pragma unroll
        for (int mi = 0; mi < 4; ++mi)
#pragma unroll
            for (int ni = 0; ni < 4; ++ni) {
                mma_bf16(acc[mi][ni], aH[mi], bH[ni]);
                mma_bf16(acc[mi][ni], aH[mi], bL[ni]);
                mma_bf16(acc[mi][ni], aL[mi], bH[ni]);
            }
    }
}

// LayerNorm of fragment-layout values -> split hi/lo into swizzled 256B-row tile.
__device__ __forceinline__ void ln_acc(const float (&v)[4][4][4],
                                       const float* gs, const float* bs,
                                       char* Ahi, char* Alo,
                                       float2* red, float2* mrs,
                                       int warp_m, int warp_n, int lane, int tid) {
    int row0 = warp_m * 64 + (lane >> 2);
    int col0 = warp_n * 32 + (lane & 3) * 2;
#pragma unroll
    for (int mi = 0; mi < 4; ++mi) {
        float s1 = 0, q1 = 0, s2 = 0, q2 = 0;
#pragma unroll
        for (int ni = 0; ni < 4; ++ni) {
            s1 += v[mi][ni][0] + v[mi][ni][1];
            q1 += v[mi][ni][0] * v[mi][ni][0] + v[mi][ni][1] * v[mi][ni][1];
            s2 += v[mi][ni][2] + v[mi][ni][3];
            q2 += v[mi][ni][2] * v[mi][ni][2] + v[mi][ni][3] * v[mi][ni][3];
        }
        s1 += __shfl_xor_sync(~0u, s1, 1); s1 += __shfl_xor_sync(~0u, s1, 2);
        q1 += __shfl_xor_sync(~0u, q1, 1); q1 += __shfl_xor_sync(~0u, q1, 2);
        s2 += __shfl_xor_sync(~0u, s2, 1); s2 += __shfl_xor_sync(~0u, s2, 2);
        q2 += __shfl_xor_sync(~0u, q2, 1); q2 += __shfl_xor_sync(~0u, q2, 2);
        if ((lane & 3) == 0) {
            int r1 = row0 + mi * 16;
            red[r1 * 4 + warp_n] = make_float2(s1, q1);
            red[(r1 + 8) * 4 + warp_n] = make_float2(s2, q2);
        }
    }
    __syncthreads();
    if (tid < 128) {
        float s = 0, q = 0;
#pragma unroll
        for (int w = 0; w < 4; ++w) { float2 p = red[tid * 4 + w]; s += p.x; q += p.y; }
        float m = s * (1.0f / 128.0f);
        float var = q * (1.0f / 128.0f) - m * m;
        mrs[tid] = make_float2(m, rsqrtf(var + EPSm));
    }
    __syncthreads();
#pragma unroll
    for (int mi = 0; mi < 4; ++mi) {
        float2 m1 = mrs[row0 + mi * 16];
        float2 m2 = mrs[row0 + mi * 16 + 8];
#pragma unroll
        for (int ni = 0; ni < 4; ++ni) {
            int col = col0 + ni * 8;
            float g0 = gs[col], g1 = gs[col + 1], bb0 = bs[col], bb1 = bs[col + 1];
            int r1 = row0 + mi * 16, r2 = r1 + 8;
            float f0 = (v[mi][ni][0] - m1.x) * m1.y * g0 + bb0;
            float f1 = (v[mi][ni][1] - m1.x) * m1.y * g1 + bb1;
            float f2 = (v[mi][ni][2] - m2.x) * m2.y * g0 + bb0;
            float f3 = (v[mi][ni][3] - m2.x) * m2.y * g1 + bb1;
            uint32_t h, l;
            uint32_t o1 = sw4(r1, col), o2 = sw4(r2, col);
            split2(f0, f1, h, l);
            *reinterpret_cast<uint32_t*>(Ahi + o1) = h;
            *reinterpret_cast<uint32_t*>(Alo + o1) = l;
            split2(f2, f3, h, l);
            *reinterpret_cast<uint32_t*>(Ahi + o2) = h;
            *reinterpret_cast<uint32_t*>(Alo + o2) = l;
        }
    }
    __syncthreads();
}

// ============================ kernels ============================

__global__ void kprep_kernel(const float* __restrict__ w1, const float* __restrict__ w2,
                             const float* __restrict__ outw) {
    int idx = blockIdx.x * 256 + threadIdx.x;
    if (idx < 65536) {                 // w1t [512 n][128 k]
        int n = idx >> 7, k = idx & 127;
        sp1(w1[k * 512 + n], &g_w1t_hi[idx], &g_w1t_lo[idx]);
    } else if (idx < 131072) {         // w2t [128 n][512 k]
        int j = idx - 65536;
        int n = j >> 9, k = j & 511;
        sp1(w2[k * 128 + n], &g_w2t_hi[j], &g_w2t_lo[j]);
    } else if (idx < 147456) {         // owt [128 n][128 k]
        int j = idx - 131072;
        int n = j >> 7, k = j & 127;
        sp1(outw[k * 128 + n], &g_owt_hi[j], &g_owt_lo[j]);
    }
}

// t=0 Gram partials: one 128-row tile per CTA; h = LN1(x); part = h^T h.
#define KG_SMEM (6144 + 65536)
__global__ void __launch_bounds__(256, 1)
kgram0(const float* __restrict__ xin,
       const float* __restrict__ lng, const float* __restrict__ lnb) {
    extern __shared__ char sm[];
    float* gs = reinterpret_cast<float*>(sm);
    float* bs = gs + 128;
    float2* red = reinterpret_cast<float2*>(sm + 1024);
    float2* mrs = reinterpret_cast<float2*>(sm + 5120);
    char* Hhi = sm + 6144;
    char* Hlo = sm + 6144 + 32768;
    uint32_t smb = smem_u32(sm);
    int tid = threadIdx.x, lane = tid & 31, wid = tid >> 5;
    int warp_m = wid & 1, warp_n = wid >> 1;
    int row0 = warp_m * 64 + (lane >> 2);
    int col0 = warp_n * 32 + (lane & 3) * 2;
    if (tid < 128) { gs[tid] = lng[tid]; bs[tid] = lnb[tid]; }
    __syncthreads();

    const float* xt = xin + (size_t)blockIdx.x * 16384;
    float v[4][4][4];
#pragma unroll
    for (int mi = 0; mi < 4; ++mi)
#pragma unroll
        for (int ni = 0; ni < 4; ++ni) {
            const float* p = xt + (row0 + mi * 16) * 128 + col0 + ni * 8;
            float2 a = *reinterpret_cast<const float2*>(p);
            float2 b = *reinterpret_cast<const float2*>(p + 8 * 128);
            v[mi][ni][0] = a.x; v[mi][ni][1] = a.y;
            v[mi][ni][2] = b.x; v[mi][ni][3] = b.y;
        }
    ln_acc(v, gs, bs, Hhi, Hlo, red, mrs, warp_m, warp_n, lane, tid);

    float acc[4][4][4];
#pragma unroll
    for (int mi = 0; mi < 4; ++mi)
#pragma unroll
        for (int ni = 0; ni < 4; ++ni)
#pragma unroll
            for (int e = 0; e < 4; ++e) acc[mi][ni][e] = 0.f;
    mma_tt(acc, smb + 6144, smb + 6144 + 32768, warp_m, warp_n, lane);

    float* dst = g_part + (size_t)blockIdx.x * 16384;
#pragma unroll
    for (int mi = 0; mi < 4; ++mi)
#pragma unroll
        for (int ni = 0; ni < 4; ++ni) {
            int r1 = row0 + mi * 16, col = col0 + ni * 8;
            *reinterpret_cast<float2*>(dst + r1 * 128 + col) =
                make_float2(acc[mi][ni][0], acc[mi][ni][1]);
            *reinterpret_cast<float2*>(dst + (r1 + 8) * 128 + col) =
                make_float2(acc[mi][ni][2], acc[mi][ni][3]);
        }
}

// stage-1 reduce: 1024 partials -> 64 partials. 1M threads, 16 loads each.
__global__ void kred1_kernel() {
    int idx = blockIdx.x * 256 + threadIdx.x;
    int e = idx & 16383;
    int g = idx >> 14;
    const float* p = g_part + (size_t)g * 16 * 16384 + e;
    float s = 0.f;
#pragma unroll
    for (int i = 0; i < 16; ++i) s += p[(size_t)i * 16384];
    g_part2[(size_t)g * 16384 + e] = s;
}

// one-shot QK = Qw @ Kw^T (launch-time prep)
#define TS_SMEM (128 * 129 * 4 + 512 * 4)
__global__ void __launch_bounds__(256, 1)
kqk_kernel(const float* __restrict__ A, const float* __restrict__ B) {
    extern __shared__ float ts[];
    float* Bs = ts;
    float* As = ts + 128 * 129;
    int tid = threadIdx.x;
    for (int idx = tid; idx < 16384; idx += 256)
        Bs[(idx >> 7) * 129 + (idx & 127)] = B[idx];
    int r0 = blockIdx.x * 4;
    for (int idx = tid; idx < 512; idx += 256)
        As[idx] = A[(r0 + (idx >> 7)) * 128 + (idx & 127)];
    __syncthreads();
    int j = tid & 127, i0 = (tid >> 7) * 2;
    float c0 = 0.f, c1 = 0.f;
#pragma unroll 8
    for (int k = 0; k < 128; ++k) {
        float b = Bs[j * 129 + k];
        c0 = fmaf(As[i0 * 128 + k], b, c0);
        c1 = fmaf(As[i0 * 128 + 128 + k], b, c1);
    }
    g_QK[(r0 + i0) * 128 + j] = c0;
    g_QK[(r0 + i0 + 1) * 128 + j] = c1;
}

// fused per-step mid kernel: phase1 T1 = G@Vw (G reduced from g_part2),
// global barrier (32 resident CTAs), phase2 Mt = split(QK @ T1).
__global__ void __launch_bounds__(256, 1)
kmid_kernel(const float* __restrict__ Vw) {
    extern __shared__ float ts[];
    float* Bs = ts;
    float* As = ts + 128 * 129;
    int tid = threadIdx.x;
    int r0 = blockIdx.x * 4;
    int j = tid & 127, i0 = (tid >> 7) * 2;

    // ---- phase 1: T1 = G @ Vw ----
    for (int idx = tid; idx < 16384; idx += 256)
        Bs[(idx >> 7) * 129 + (idx & 127)] = Vw[idx];
    for (int idx = tid; idx < 512; idx += 256) {
        int off = (r0 + (idx >> 7)) * 128 + (idx & 127);
        const float* p = g_part2 + off;
        float s = 0.f;
#pragma unroll 8
        for (int g = 0; g < 64; ++g) s += p[(size_t)g * 16384];
        As[idx] = s;
    }
    __syncthreads();
    {
        float c0 = 0.f, c1 = 0.f;
#pragma unroll 8
        for (int k = 0; k < 128; ++k) {
            float b = Bs[k * 129 + j];
            c0 = fmaf(As[i0 * 128 + k], b, c0);
            c1 = fmaf(As[i0 * 128 + 128 + k], b, c1);
        }
        g_T1[(r0 + i0) * 128 + j] = c0;
        g_T1[(r0 + i0 + 1) * 128 + j] = c1;
    }
    // ---- global barrier (all 32 CTAs resident; monotonic ticket) ----
    __threadfence();
    __syncthreads();
    if (tid == 0) {
        unsigned arrive = atomicAdd(&g_barrier, 1u);
        unsigned target = (arrive / 32u + 1u) * 32u;
        while (*reinterpret_cast<volatile unsigned*>(&g_barrier) < target)
            __nanosleep(64);
        __threadfence();
    }
    __syncthreads();
    // ---- phase 2: Mt = split(QK @ T1) ----
    for (int idx = tid; idx < 16384; idx += 256)
        Bs[(idx >> 7) * 129 + (idx & 127)] = __ldcg(g_T1 + idx);
    for (int idx = tid; idx < 512; idx += 256)
        As[idx] = g_QK[(r0 + (idx >> 7)) * 128 + (idx & 127)];
    __syncthreads();
    {
        float c0 = 0.f, c1 = 0.f;
#pragma unroll 8
        for (int k = 0; k < 128; ++k) {
            float b = Bs[k * 129 + j];
            c0 = fmaf(As[i0 * 128 + k], b, c0);
            c1 = fmaf(As[i0 * 128 + 128 + k], b, c1);
        }
        sp1(c0, &g_Mt_hi[j * 128 + r0 + i0], &g_Mt_lo[j * 128 + r0 + i0]);
        sp1(c1, &g_Mt_hi[j * 128 + r0 + i0 + 1], &g_Mt_lo[j * 128 + r0 + i0 + 1]);
    }
}

// ================= big fused kernel (HMMA + cp.async, 2-sync FF pipeline) =================
#define KC_RED  5120
#define KC_MRS  9216
#define KC_A    10240                  // Ahi 32K | Alo 32K
#define KC_B0   (KC_A + 65536)         // 32K (hi at +0, lo at +16384 for FF tiles)
#define KC_B1   (KC_B0 + 32768)
#define KC_F    (KC_B1 + 32768)        // Fhi 16K | Flo 16K
#define KC_SMEM (KC_F + 32768)         // 174080

__global__ void __launch_bounds__(256, 1)
kc_mma(const float* __restrict__ xin, int srcIsG,
       const float* __restrict__ ln1g, const float* __restrict__ ln1b,
       const float* __restrict__ ln2g, const float* __restrict__ ln2b,
       const float* __restrict__ b1, const float* __restrict__ b2,
       const float* __restrict__ outb, float* __restrict__ outp, int last) {
    extern __shared__ char sm[];
    uint32_t smb = smem_u32(sm);
    int tid = threadIdx.x, lane = tid & 31, wid = tid >> 5;
    int warp_m = wid & 1, warp_n = wid >> 1;
    int row0 = warp_m * 64 + (lane >> 2);
    int col0 = warp_n * 32 + (lane & 3) * 2;

    float* ln1gs = reinterpret_cast<float*>(sm);
    float* ln1bs = ln1gs + 128;
    float* ln2gs = ln1gs + 256;
    float* ln2bs = ln1gs + 384;
    float* b2s   = ln1gs + 512;
    float* outbs = ln1gs + 640;
    float* b1s   = ln1gs + 768;     // 512 floats
    float2* red  = reinterpret_cast<float2*>(sm + KC_RED);
    float2* mrs  = reinterpret_cast<float2*>(sm + KC_MRS);
    if (tid < 128) {
        ln1gs[tid] = ln1g[tid]; ln1bs[tid] = ln1b[tid];
        ln2gs[tid] = ln2g[tid]; ln2bs[tid] = ln2b[tid];
        b2s[tid] = b2[tid]; outbs[tid] = outb[tid];
    }
    b1s[tid] = b1[tid]; b1s[tid + 256] = b1[tid + 256];

    // prefetch Mt (hi -> B0, lo -> B1), overlapped with x load + LN1
    cp_tile256(smb + KC_B0, reinterpret_cast<const uint4*>(g_Mt_hi), 128, 16, tid);
    cp_tile256(smb + KC_B1, reinterpret_cast<const uint4*>(g_Mt_lo), 128, 16, tid);
    cpa_commit();

    // x in fragment layout
    size_t base = (size_t)blockIdx.x * 16384;
    const float* xt = (srcIsG ? g_x : xin) + base;
    float xr[4][4][4];
#pragma unroll
    for (int mi = 0; mi < 4; ++mi)
#pragma unroll
        for (int ni = 0; ni < 4; ++ni) {
            const float* p = xt + (row0 + mi * 16) * 128 + col0 + ni * 8;
            float2 a = *reinterpret_cast<const float2*>(p);
            float2 b = *reinterpret_cast<const float2*>(p + 8 * 128);
            xr[mi][ni][0] = a.x; xr[mi][ni][1] = a.y;
            xr[mi][ni][2] = b.x; xr[mi][ni][3] = b.y;
        }

    // A <- LN1(x)
    ln_acc(xr, ln1gs, ln1bs, sm + KC_A, sm + KC_A + 32768, red, mrs, warp_m, warp_n, lane, tid);
    cpa_wait<0>();
    __syncthreads();
    // x += h @ M
    mma_nt(xr, smb + KC_A, smb + KC_A + 32768, smb + KC_B0, smb + KC_B1, warp_m, warp_n, lane);
    __syncthreads();

    // prime FF pipeline: w1 sub-chunk 0 -> B0
    cp_tile256(smb + KC_B0,         reinterpret_cast<const uint4*>(g_w1t_hi), 64, 16, tid);
    cp_tile256(smb + KC_B0 + 16384, reinterpret_cast<const uint4*>(g_w1t_lo), 64, 16, tid);
    cpa_commit();

    // A <- LN2(x)
    ln_acc(xr, ln2gs, ln2bs, sm + KC_A, sm + KC_A + 32768, red, mrs, warp_m, warp_n, lane, tid);
    cpa_wait<0>();       // w1_0 landed
    __syncthreads();     // w1_0 visible

    // FF: 8 sub-chunks of 64 hidden units, double-buffered weights, 2 syncs/iter
#pragma unroll 1
    for (int c = 0; c < 8; ++c) {
        // prefetch w2_c -> B1 (overlaps mma1 + relu)
        cp_tile128(smb + KC_B1,         reinterpret_cast<const uint4*>(g_w2t_hi) + c * 8, 64, tid);
        cp_tile128(smb + KC_B1 + 16384, reinterpret_cast<const uint4*>(g_w2t_lo) + c * 8, 64, tid);
        cpa_commit();
        float u[4][2][4];
#pragma unroll
        for (int mi = 0; mi < 4; ++mi)
#pragma unroll
            for (int ni = 0; ni < 2; ++ni)
#pragma unroll
                for (int e = 0; e < 4; ++e) u[mi][ni][e] = 0.f;
        mma_n64(u, smb + KC_A, smb + KC_A + 32768, smb + KC_B0, smb + KC_B0 + 16384,
                warp_m, warp_n, lane);
        // bias + relu + split -> F
#pragma unroll
        for (int mi = 0; mi < 4; ++mi)
#pragma unroll
            for (int ni = 0; ni < 2; ++ni) {
                int hcol = warp_n * 16 + (lane & 3) * 2 + ni * 8;      // 0..63
                float bb0 = b1s[c * 64 + hcol], bb1 = b1s[c * 64 + hcol + 1];
                int r1 = row0 + mi * 16, r2 = r1 + 8;
                float f0 = fmaxf(u[mi][ni][0] + bb0, 0.f);
                float f1 = fmaxf(u[mi][ni][1] + bb1, 0.f);
                float f2 = fmaxf(u[mi][ni][2] + bb0, 0.f);
                float f3 = fmaxf(u[mi][ni][3] + bb1, 0.f);
                uint32_t h, l;
                uint32_t o1 = sw4_64(r1, hcol), o2 = sw4_64(r2, hcol);
                split2(f0, f1, h, l);
                *reinterpret_cast<uint32_t*>(sm + KC_F + o1) = h;
                *reinterpret_cast<uint32_t*>(sm + KC_F + 16384 + o1) = l;
                split2(f2, f3, h, l);
                *reinterpret_cast<uint32_t*>(sm + KC_F + o2) = h;
                *reinterpret_cast<uint32_t*>(sm + KC_F + 16384 + o2) = l;
            }
        cpa_wait<0>();       // w2_c landed
        __syncthreads();     // F + w2_c visible; B0 (w1_c) free
        // prefetch w1_{c+1} -> B0 (overlaps mma2); last iter: owt_hi if needed
        if (c < 7) {
            cp_tile256(smb + KC_B0,         reinterpret_cast<const uint4*>(g_w1t_hi) + (c + 1) * 1024, 64, 16, tid);
            cp_tile256(smb + KC_B0 + 16384, reinterpret_cast<const uint4*>(g_w1t_lo) + (c + 1) * 1024, 64, 16, tid);
        } else if (last) {
            cp_tile256(smb + KC_B0, reinterpret_cast<const uint4*>(g_owt_hi), 128, 16, tid);
        }
        cpa_commit();
        mma_k64(xr, smb + KC_F, smb + KC_F + 16384, smb + KC_B1, smb + KC_B1 + 16384,
                warp_m, warp_n, lane);
        cpa_wait<0>();       // w1_{c+1} (or owt_hi) landed
        __syncthreads();     // B1/F free; next tile visible
    }

    // + b2
#pragma unroll
    for (int mi = 0; mi < 4; ++mi)
#pragma unroll
        for (int ni = 0; ni < 4; ++ni) {
            int col = col0 + ni * 8;
            xr[mi][ni][0] += b2s[col];     xr[mi][ni][1] += b2s[col + 1];
            xr[mi][ni][2] += b2s[col];     xr[mi][ni][3] += b2s[col + 1];
        }

    if (!last) {
        // store x_new
        float* dst = g_x + base;
#pragma unroll
        for (int mi = 0; mi < 4; ++mi)
#pragma unroll
            for (int ni = 0; ni < 4; ++ni) {
                int r1 = row0 + mi * 16, col = col0 + ni * 8;
                *reinterpret_cast<float2*>(dst + r1 * 128 + col) =
                    make_float2(xr[mi][ni][0], xr[mi][ni][1]);
                *reinterpret_cast<float2*>(dst + (r1 + 8) * 128 + col) =
                    make_float2(xr[mi][ni][2], xr[mi][ni][3]);
            }
        // fused Gram partial for the NEXT step: h = LN1(x_new); part = h^T h
        ln_acc(xr, ln1gs, ln1bs, sm + KC_A, sm + KC_A + 32768, red, mrs, warp_m, warp_n, lane, tid);
        float ga[4][4][4];
#pragma unroll
        for (int mi = 0; mi < 4; ++mi)
#pragma unroll
            for (int ni = 0; ni < 4; ++ni)
#pragma unroll
                for (int e = 0; e < 4; ++e) ga[mi][ni][e] = 0.f;
        mma_tt(ga, smb + KC_A, smb + KC_A + 32768, warp_m, warp_n, lane);
        float* pdst = g_part + (size_t)blockIdx.x * 16384;
#pragma unroll
        for (int mi = 0; mi < 4; ++mi)
#pragma unroll
            for (int ni = 0; ni < 4; ++ni) {
                int r1 = row0 + mi * 16, col = col0 + ni * 8;
                *reinterpret_cast<float2*>(pdst + r1 * 128 + col) =
                    make_float2(ga[mi][ni][0], ga[mi][ni][1]);
                *reinterpret_cast<float2*>(pdst + (r1 + 8) * 128 + col) =
                    make_float2(ga[mi][ni][2], ga[mi][ni][3]);
            }
    } else {
        // out = x @ outw + outb  (owt_hi already landed in B0 at loop end)
        cp_tile256(smb + KC_B1, reinterpret_cast<const uint4*>(g_owt_lo), 128, 16, tid);
        cpa_commit();
        // split x -> A
#pragma unroll
        for (int mi = 0; mi < 4; ++mi)
#pragma unroll
            for (int ni = 0; ni < 4; ++ni) {
                int col = col0 + ni * 8;
                int r1 = row0 + mi * 16, r2 = r1 + 8;
                uint32_t h, l;
                uint32_t o1 = sw4(r1, col), o2 = sw4(r2, col);
                split2(xr[mi][ni][0], xr[mi][ni][1], h, l);
                *reinterpret_cast<uint32_t*>(sm + KC_A + o1) = h;
                *reinterpret_cast<uint32_t*>(sm + KC_A + 32768 + o1) = l;
                split2(xr[mi][ni][2], xr[mi][ni][3], h, l);
                *reinterpret_cast<uint32_t*>(sm + KC_A + o2) = h;
                *reinterpret_cast<uint32_t*>(sm + KC_A + 32768 + o2) = l;
            }
        cpa_wait<0>();
        __syncthreads();
        float o[4][4][4];
#pragma unroll
        for (int mi = 0; mi < 4; ++mi)
#pragma unroll
            for (int ni = 0; ni < 4; ++ni)
#pragma unroll
                for (int e = 0; e < 4; ++e) o[mi][ni][e] = 0.f;
        mma_nt(o, smb + KC_A, smb + KC_A + 32768, smb + KC_B0, smb + KC_B1, warp_m, warp_n, lane);
        float* dst = outp + base;
#pragma unroll
        for (int mi = 0; mi < 4; ++mi)
#pragma unroll
            for (int ni = 0; ni < 4; ++ni) {
                int r1 = row0 + mi * 16, col = col0 + ni * 8;
                *reinterpret_cast<float2*>(dst + r1 * 128 + col) =
                    make_float2(o[mi][ni][0] + outbs[col], o[mi][ni][1] + outbs[col + 1]);
                *reinterpret_cast<float2*>(dst + (r1 + 8) * 128 + col) =
                    make_float2(o[mi][ni][2] + outbs[col], o[mi][ni][3] + outbs[col + 1]);
            }
    }
}

// ============================ host launcher ============================
extern "C" void kernel_launch(void* const* d_in, const int* in_sizes, int n_in,
                              void* d_out, int out_size) {
    (void)in_sizes; (void)n_in; (void)out_size;
    const float* x    = (const float*)d_in[0];
    const float* Kw   = (const float*)d_in[1];
    const float* Qw   = (const float*)d_in[2];
    const float* Vw   = (const float*)d_in[3];
    const float* ln1g = (const float*)d_in[4];
    const float* ln1b = (const float*)d_in[5];
    const float* ln2g = (const float*)d_in[6];
    const float* ln2b = (const float*)d_in[7];
    const float* w1   = (const float*)d_in[8];
    const float* b1   = (const float*)d_in[9];
    const float* w2   = (const float*)d_in[10];
    const float* b2   = (const float*)d_in[11];
    const float* outw = (const float*)d_in[12];
    const float* outb = (const float*)d_in[13];
    float* out = (float*)d_out;

    cudaFuncSetAttribute(kc_mma, cudaFuncAttributeMaxDynamicSharedMemorySize, KC_SMEM);
    cudaFuncSetAttribute(kgram0, cudaFuncAttributeMaxDynamicSharedMemorySize, KG_SMEM);
    cudaFuncSetAttribute(kqk_kernel, cudaFuncAttributeMaxDynamicSharedMemorySize, TS_SMEM);
    cudaFuncSetAttribute(kmid_kernel, cudaFuncAttributeMaxDynamicSharedMemorySize, TS_SMEM);

    kprep_kernel<<<576, 256>>>(w1, w2, outw);
    kqk_kernel<<<32, 256, TS_SMEM>>>(Qw, Kw);         // QK = Qw @ Kw^T
    kgram0<<<NTILESm, 256, KG_SMEM>>>(x, ln1g, ln1b);

    for (int t = 0; t < 4; ++t) {
        int srcIsG = (t != 0);
        kred1_kernel<<<4096, 256>>>();                // 1024 -> 64 partials
        kmid_kernel<<<32, 256, TS_SMEM>>>(Vw);        // T1 = G@Vw ; Mt = split(QK@T1)
        kc_mma<<<NTILESm, 256, KC_SMEM>>>(x, srcIsG, ln1g, ln1b, ln2g, ln2b,
                                          b1, b2, outb, out, t == 3);
    }
}

// round 11
// speedup vs baseline: 1.2887x; 1.0125x over previous
#include <cuda_runtime.h>
#include <cuda_bf16.h>
#include <cstdint>

#define EPSm   1e-5f
#define NROWSm 131072
#define NTILESm 1024
#define NPART  1024

// ---------------- device scratch ----------------
__device__ float g_x[NROWSm * 128];
__device__ float g_part[NPART * 128 * 128];   // 64 MB gram partials (stage 0)
__device__ float g_part2[8 * 128 * 128];      // 512 KB (stage 1)
__device__ float g_QK[128 * 128];
__device__ float g_T1[128 * 128];
__device__ unsigned g_barrier;                // monotonic ticket barrier for kmid
__device__ __nv_bfloat16 g_Mt_hi[128 * 128],  g_Mt_lo[128 * 128];
__device__ __nv_bfloat16 g_w1t_hi[512 * 128], g_w1t_lo[512 * 128];   // [512 n][128 k]
__device__ __nv_bfloat16 g_w2t_hi[128 * 512], g_w2t_lo[128 * 512];   // [128 n][512 k]
__device__ __nv_bfloat16 g_owt_hi[128 * 128], g_owt_lo[128 * 128];

// ---------------- helpers ----------------
__device__ __forceinline__ uint32_t smem_u32(const void* p) {
    uint32_t a;
    asm("{ .reg .u64 t; cvta.to.shared.u64 t, %1; cvt.u32.u64 %0, t; }" : "=r"(a) : "l"(p));
    return a;
}
// XOR-swizzled tile, 256B rows (128 bf16 cols)
__device__ __forceinline__ uint32_t sw16(int r, int c8) {
    return (uint32_t)(r * 256 + ((c8 ^ (r & 7)) << 4));
}
__device__ __forceinline__ uint32_t sw4(int r, int col) {
    return (uint32_t)(r * 256 + ((((col >> 3) ^ (r & 7)) << 4)) + (col & 7) * 2);
}
// XOR-swizzled tile, 128B rows (64 bf16 cols)
__device__ __forceinline__ uint32_t sw16_64(int r, int c8) {
    return (uint32_t)(r * 128 + ((((c8 ^ (r & 7)) & 7) << 4)));
}
__device__ __forceinline__ uint32_t sw4_64(int r, int col) {
    return (uint32_t)(r * 128 + ((((col >> 3) ^ (r & 7)) & 7) << 4) + (col & 7) * 2);
}
__device__ __forceinline__ void split2(float f0, float f1, uint32_t& hi, uint32_t& lo) {
    __nv_bfloat162 H = __floats2bfloat162_rn(f0, f1);
    float r0 = f0 - __bfloat162float(H.x);
    float r1 = f1 - __bfloat162float(H.y);
    __nv_bfloat162 L = __floats2bfloat162_rn(r0, r1);
    hi = *reinterpret_cast<uint32_t*>(&H);
    lo = *reinterpret_cast<uint32_t*>(&L);
}
__device__ __forceinline__ void sp1(float v, __nv_bfloat16* h, __nv_bfloat16* l) {
    __nv_bfloat16 hh = __float2bfloat16(v);
    *h = hh;
    *l = __float2bfloat16(v - __bfloat162float(hh));
}
__device__ __forceinline__ void ldsm4(uint32_t* r, uint32_t a) {
    asm volatile("ldmatrix.sync.aligned.m8n8.x4.shared.b16 {%0,%1,%2,%3}, [%4];"
                 : "=r"(r[0]), "=r"(r[1]), "=r"(r[2]), "=r"(r[3]) : "r"(a));
}
__device__ __forceinline__ void ldsm2(uint32_t* r, uint32_t a) {
    asm volatile("ldmatrix.sync.aligned.m8n8.x2.shared.b16 {%0,%1}, [%2];"
                 : "=r"(r[0]), "=r"(r[1]) : "r"(a));
}
__device__ __forceinline__ void ldsm4t(uint32_t* r, uint32_t a) {
    asm volatile("ldmatrix.sync.aligned.m8n8.x4.trans.shared.b16 {%0,%1,%2,%3}, [%4];"
                 : "=r"(r[0]), "=r"(r[1]), "=r"(r[2]), "=r"(r[3]) : "r"(a));
}
__device__ __forceinline__ void ldsm2t(uint32_t* r, uint32_t a) {
    asm volatile("ldmatrix.sync.aligned.m8n8.x2.trans.shared.b16 {%0,%1}, [%2];"
                 : "=r"(r[0]), "=r"(r[1]) : "r"(a));
}
__device__ __forceinline__ void mma_bf16(float* c, const uint32_t* a, const uint32_t* b) {
    asm volatile(
        "mma.sync.aligned.m16n8k16.row.col.f32.bf16.bf16.f32 "
        "{%0,%1,%2,%3}, {%4,%5,%6,%7}, {%8,%9}, {%0,%1,%2,%3};"
        : "+f"(c[0]), "+f"(c[1]), "+f"(c[2]), "+f"(c[3])
        : "r"(a[0]), "r"(a[1]), "r"(a[2]), "r"(a[3]), "r"(b[0]), "r"(b[1]));
}
// ---- cp.async ----
__device__ __forceinline__ void cpa16(uint32_t dst, const void* src) {
    asm volatile("cp.async.cg.shared.global [%0], [%1], 16;" :: "r"(dst), "l"(src));
}
__device__ __forceinline__ void cpa_commit() { asm volatile("cp.async.commit_group;"); }
template<int N> __device__ __forceinline__ void cpa_wait() {
    asm volatile("cp.async.wait_group %0;" :: "n"(N));
}
// nrows x 256B swizzled tile via cp.async (256 threads)
__device__ __forceinline__ void cp_tile256(uint32_t dst, const uint4* __restrict__ src,
                                           int nrows, int rs_u4, int tid) {
    int n = nrows * 16;
    for (int idx = tid; idx < n; idx += 256) {
        int r = idx >> 4, c8 = idx & 15;
        cpa16(dst + sw16(r, c8), src + r * rs_u4 + c8);
    }
}
// 128 rows x 128B swizzled tile via cp.async
__device__ __forceinline__ void cp_tile128(uint32_t dst, const uint4* __restrict__ src,
                                           int rs_u4, int tid) {
#pragma unroll
    for (int i = 0; i < 4; ++i) {
        int idx = tid + i * 256;
        int r = idx >> 3, c8 = idx & 7;
        cpa16(dst + sw16_64(r, c8), src + r * rs_u4 + c8);
    }
}

// C[128][128] += A(128x128k) @ Bt(128n x 128k)^T, bf16 3-split (256B-row tiles)
__device__ __forceinline__ void mma_nt(float (&acc)[4][4][4],
                                       uint32_t aHi, uint32_t aLo,
                                       uint32_t bHi, uint32_t bLo,
                                       int warp_m, int warp_n, int lane) {
#pragma unroll
    for (int k8 = 0; k8 < 8; ++k8) {
        uint32_t aH[4][4], aL[4][4], bH[4][2], bL[4][2];
        int ar = warp_m * 64 + (lane & 15);
        int ac8 = k8 * 2 + (lane >> 4);
#pragma unroll
        for (int mi = 0; mi < 4; ++mi) {
            uint32_t off = sw16(ar + mi * 16, ac8);
            ldsm4(aH[mi], aHi + off);
            ldsm4(aL[mi], aLo + off);
        }
        int l15 = lane & 15;
        int br = warp_n * 32 + (l15 & 7);
        int bc8 = k8 * 2 + (l15 >> 3);
#pragma unroll
        for (int ni = 0; ni < 4; ++ni) {
            uint32_t off = sw16(br + ni * 8, bc8);
            ldsm2(bH[ni], bHi + off);
            ldsm2(bL[ni], bLo + off);
        }
#pragma unroll
        for (int mi = 0; mi < 4; ++mi)
#pragma unroll
            for (int ni = 0; ni < 4; ++ni) {
                mma_bf16(acc[mi][ni], aH[mi], bH[ni]);
                mma_bf16(acc[mi][ni], aH[mi], bL[ni]);
                mma_bf16(acc[mi][ni], aL[mi], bH[ni]);
            }
    }
}

// u[128][64] = A(128x128k) @ Bt(64n x 128k)^T  (B tile 64 rows, 256B rows)
__device__ __forceinline__ void mma_n64(float (&u)[4][2][4],
                                        uint32_t aHi, uint32_t aLo,
                                        uint32_t bHi, uint32_t bLo,
                                        int warp_m, int warp_n, int lane) {
#pragma unroll
    for (int k8 = 0; k8 < 8; ++k8) {
        uint32_t aH[4][4], aL[4][4], bH[2][2], bL[2][2];
        int ar = warp_m * 64 + (lane & 15);
        int ac8 = k8 * 2 + (lane >> 4);
#pragma unroll
        for (int mi = 0; mi < 4; ++mi) {
            uint32_t off = sw16(ar + mi * 16, ac8);
            ldsm4(aH[mi], aHi + off);
            ldsm4(aL[mi], aLo + off);
        }
        int l15 = lane & 15;
        int br = warp_n * 16 + (l15 & 7);
        int bc8 = k8 * 2 + (l15 >> 3);
#pragma unroll
        for (int ni = 0; ni < 2; ++ni) {
            uint32_t off = sw16(br + ni * 8, bc8);
            ldsm2(bH[ni], bHi + off);
            ldsm2(bL[ni], bLo + off);
        }
#pragma unroll
        for (int mi = 0; mi < 4; ++mi)
#pragma unroll
            for (int ni = 0; ni < 2; ++ni) {
                mma_bf16(u[mi][ni], aH[mi], bH[ni]);
                mma_bf16(u[mi][ni], aH[mi], bL[ni]);
                mma_bf16(u[mi][ni], aL[mi], bH[ni]);
            }
    }
}

// C[128][128] += F(128m x 64k) @ Bt(128n x 64k)^T  (128B-row tiles)
__device__ __forceinline__ void mma_k64(float (&acc)[4][4][4],
                                        uint32_t fHi, uint32_t fLo,
                                        uint32_t bHi, uint32_t bLo,
                                        int warp_m, int warp_n, int lane) {
#pragma unroll
    for (int k8 = 0; k8 < 4; ++k8) {
        uint32_t aH[4][4], aL[4][4], bH[4][2], bL[4][2];
        int ar = warp_m * 64 + (lane & 15);
        int ac8 = k8 * 2 + (lane >> 4);
#pragma unroll
        for (int mi = 0; mi < 4; ++mi) {
            uint32_t off = sw16_64(ar + mi * 16, ac8);
            ldsm4(aH[mi], fHi + off);
            ldsm4(aL[mi], fLo + off);
        }
        int l15 = lane & 15;
        int br = warp_n * 32 + (l15 & 7);
        int bc8 = k8 * 2 + (l15 >> 3);
#pragma unroll
        for (int ni = 0; ni < 4; ++ni) {
            uint32_t off = sw16_64(br + ni * 8, bc8);
            ldsm2(bH[ni], bHi + off);
            ldsm2(bL[ni], bLo + off);
        }
#pragma unroll
        for (int mi = 0; mi < 4; ++mi)
#pragma unroll
            for (int ni = 0; ni < 4; ++ni) {
                mma_bf16(acc[mi][ni], aH[mi], bH[ni]);
                mma_bf16(acc[mi][ni], aH[mi], bL[ni]);
                mma_bf16(acc[mi][ni], aL[mi], bH[ni]);
            }
    }
}

// Gram: C += H^T @ H, bf16 3-split; trans loads of row-major H tile.
__device__ __forceinline__ void mma_tt(float (&acc)[4][4][4],
                                       uint32_t hHi, uint32_t hLo,
                                       int warp_m, int warp_n, int lane) {
#pragma unroll
    for (int k8 = 0; k8 < 8; ++k8) {
        int k0 = k8 * 16;
        uint32_t aH[4][4], aL[4][4], bH[4][2], bL[4][2];
        int ar = k0 + (lane & 7) + ((lane >> 4) << 3);
        int asel = (lane >> 3) & 1;
#pragma unroll
        for (int mi = 0; mi < 4; ++mi) {
            int c8 = ((warp_m * 64 + mi * 16) >> 3) + asel;
            uint32_t off = sw16(ar, c8);
            ldsm4t(aH[mi], hHi + off);
            ldsm4t(aL[mi], hLo + off);
        }
        int l15 = lane & 15;
        int br = k0 + (l15 & 7) + ((l15 >> 3) << 3);
#pragma unroll
        for (int ni = 0; ni < 4; ++ni) {
            int c8 = (warp_n * 32 + ni * 8) >> 3;
            uint32_t off = sw16(br, c8);
            ldsm2t(bH[ni], hHi + off);
            ldsm2t(bL[ni], hLo + off);
        }
#pragma unroll
        for (int mi = 0; mi < 4; ++mi)
#pragma unroll
            for (int ni = 0; ni < 4; ++ni) {
                mma_bf16(acc[mi][ni], aH[mi], bH[ni]);
                mma_bf16(acc[mi][ni], aH[mi], bL[ni]);
                mma_bf16(acc[mi][ni], aL[mi], bH[ni]);
            }
    }
}

// LayerNorm of fragment-layout values -> split hi/lo into swizzled 256B-row tile.
__device__ __forceinline__ void ln_acc(const float (&v)[4][4][4],
                                       const float* gs, const float* bs,
                                       char* Ahi, char* Alo,
                                       float2* red, float2* mrs,
                                       int warp_m, int warp_n, int lane, int tid) {
    int row0 = warp_m * 64 + (lane >> 2);
    int col0 = warp_n * 32 + (lane & 3) * 2;
#pragma unroll
    for (int mi = 0; mi < 4; ++mi) {
        float s1 = 0, q1 = 0, s2 = 0, q2 = 0;
#pragma unroll
        for (int ni = 0; ni < 4; ++ni) {
            s1 += v[mi][ni][0] + v[mi][ni][1];
            q1 += v[mi][ni][0] * v[mi][ni][0] + v[mi][ni][1] * v[mi][ni][1];
            s2 += v[mi][ni][2] + v[mi][ni][3];
            q2 += v[mi][ni][2] * v[mi][ni][2] + v[mi][ni][3] * v[mi][ni][3];
        }
        s1 += __shfl_xor_sync(~0u, s1, 1); s1 += __shfl_xor_sync(~0u, s1, 2);
        q1 += __shfl_xor_sync(~0u, q1, 1); q1 += __shfl_xor_sync(~0u, q1, 2);
        s2 += __shfl_xor_sync(~0u, s2, 1); s2 += __shfl_xor_sync(~0u, s2, 2);
        q2 += __shfl_xor_sync(~0u, q2, 1); q2 += __shfl_xor_sync(~0u, q2, 2);
        if ((lane & 3) == 0) {
            int r1 = row0 + mi * 16;
            red[r1 * 4 + warp_n] = make_float2(s1, q1);
            red[(r1 + 8) * 4 + warp_n] = make_float2(s2, q2);
        }
    }
    __syncthreads();
    if (tid < 128) {
        float s = 0, q = 0;
#pragma unroll
        for (int w = 0; w < 4; ++w) { float2 p = red[tid * 4 + w]; s += p.x; q += p.y; }
        float m = s * (1.0f / 128.0f);
        float var = q * (1.0f / 128.0f) - m * m;
        mrs[tid] = make_float2(m, rsqrtf(var + EPSm));
    }
    __syncthreads();
#pragma unroll
    for (int mi = 0; mi < 4; ++mi) {
        float2 m1 = mrs[row0 + mi * 16];
        float2 m2 = mrs[row0 + mi * 16 + 8];
#pragma unroll
        for (int ni = 0; ni < 4; ++ni) {
            int col = col0 + ni * 8;
            float g0 = gs[col], g1 = gs[col + 1], bb0 = bs[col], bb1 = bs[col + 1];
            int r1 = row0 + mi * 16, r2 = r1 + 8;
            float f0 = (v[mi][ni][0] - m1.x) * m1.y * g0 + bb0;
            float f1 = (v[mi][ni][1] - m1.x) * m1.y * g1 + bb1;
            float f2 = (v[mi][ni][2] - m2.x) * m2.y * g0 + bb0;
            float f3 = (v[mi][ni][3] - m2.x) * m2.y * g1 + bb1;
            uint32_t h, l;
            uint32_t o1 = sw4(r1, col), o2 = sw4(r2, col);
            split2(f0, f1, h, l);
            *reinterpret_cast<uint32_t*>(Ahi + o1) = h;
            *reinterpret_cast<uint32_t*>(Alo + o1) = l;
            split2(f2, f3, h, l);
            *reinterpret_cast<uint32_t*>(Ahi + o2) = h;
            *reinterpret_cast<uint32_t*>(Alo + o2) = l;
        }
    }
    __syncthreads();
}

// ============================ kernels ============================

__global__ void kprep_kernel(const float* __restrict__ w1, const float* __restrict__ w2,
                             const float* __restrict__ outw) {
    int idx = blockIdx.x * 256 + threadIdx.x;
    if (idx < 65536) {                 // w1t [512 n][128 k]
        int n = idx >> 7, k = idx & 127;
        sp1(w1[k * 512 + n], &g_w1t_hi[idx], &g_w1t_lo[idx]);
    } else if (idx < 131072) {         // w2t [128 n][512 k]
        int j = idx - 65536;
        int n = j >> 9, k = j & 511;
        sp1(w2[k * 128 + n], &g_w2t_hi[j], &g_w2t_lo[j]);
    } else if (idx < 147456) {         // owt [128 n][128 k]
        int j = idx - 131072;
        int n = j >> 7, k = j & 127;
        sp1(outw[k * 128 + n], &g_owt_hi[j], &g_owt_lo[j]);
    }
}

// t=0 Gram partials: one 128-row tile per CTA; h = LN1(x); part = h^T h.
#define KG_SMEM (6144 + 65536)
__global__ void __launch_bounds__(256, 1)
kgram0(const float* __restrict__ xin,
       const float* __restrict__ lng, const float* __restrict__ lnb) {
    extern __shared__ char sm[];
    float* gs = reinterpret_cast<float*>(sm);
    float* bs = gs + 128;
    float2* red = reinterpret_cast<float2*>(sm + 1024);
    float2* mrs = reinterpret_cast<float2*>(sm + 5120);
    char* Hhi = sm + 6144;
    char* Hlo = sm + 6144 + 32768;
    uint32_t smb = smem_u32(sm);
    int tid = threadIdx.x, lane = tid & 31, wid = tid >> 5;
    int warp_m = wid & 1, warp_n = wid >> 1;
    int row0 = warp_m * 64 + (lane >> 2);
    int col0 = warp_n * 32 + (lane & 3) * 2;
    if (tid < 128) { gs[tid] = lng[tid]; bs[tid] = lnb[tid]; }
    __syncthreads();

    const float* xt = xin + (size_t)blockIdx.x * 16384;
    float v[4][4][4];
#pragma unroll
    for (int mi = 0; mi < 4; ++mi)
#pragma unroll
        for (int ni = 0; ni < 4; ++ni) {
            const float* p = xt + (row0 + mi * 16) * 128 + col0 + ni * 8;
            float2 a = *reinterpret_cast<const float2*>(p);
            float2 b = *reinterpret_cast<const float2*>(p + 8 * 128);
            v[mi][ni][0] = a.x; v[mi][ni][1] = a.y;
            v[mi][ni][2] = b.x; v[mi][ni][3] = b.y;
        }
    ln_acc(v, gs, bs, Hhi, Hlo, red, mrs, warp_m, warp_n, lane, tid);

    float acc[4][4][4];
#pragma unroll
    for (int mi = 0; mi < 4; ++mi)
#pragma unroll
        for (int ni = 0; ni < 4; ++ni)
#pragma unroll
            for (int e = 0; e < 4; ++e) acc[mi][ni][e] = 0.f;
    mma_tt(acc, smb + 6144, smb + 6144 + 32768, warp_m, warp_n, lane);

    float* dst = g_part + (size_t)blockIdx.x * 16384;
#pragma unroll
    for (int mi = 0; mi < 4; ++mi)
#pragma unroll
        for (int ni = 0; ni < 4; ++ni) {
            int r1 = row0 + mi * 16, col = col0 + ni * 8;
            *reinterpret_cast<float2*>(dst + r1 * 128 + col) =
                make_float2(acc[mi][ni][0], acc[mi][ni][1]);
            *reinterpret_cast<float2*>(dst + (r1 + 8) * 128 + col) =
                make_float2(acc[mi][ni][2], acc[mi][ni][3]);
        }
}

// stage-1 reduce: 1024 partials -> 8 partials. 131072 threads, 128 loads each.
__global__ void kred1_kernel() {
    int idx = blockIdx.x * 256 + threadIdx.x;   // 0 .. 131071
    int e = idx & 16383;
    int g = idx >> 14;                           // 0..7
    const float* p = g_part + (size_t)g * 128 * 16384 + e;
    float s0 = 0.f, s1 = 0.f, s2 = 0.f, s3 = 0.f;
#pragma unroll 8
    for (int i = 0; i < 128; i += 4) {
        s0 += p[(size_t)(i + 0) * 16384];
        s1 += p[(size_t)(i + 1) * 16384];
        s2 += p[(size_t)(i + 2) * 16384];
        s3 += p[(size_t)(i + 3) * 16384];
    }
    g_part2[(size_t)g * 16384 + e] = (s0 + s1) + (s2 + s3);
}

// one-shot QK = Qw @ Kw^T (launch-time prep)
#define TS_SMEM (128 * 129 * 4 + 512 * 4)
__global__ void __launch_bounds__(256, 1)
kqk_kernel(const float* __restrict__ A, const float* __restrict__ B) {
    extern __shared__ float ts[];
    float* Bs = ts;
    float* As = ts + 128 * 129;
    int tid = threadIdx.x;
    for (int idx = tid; idx < 16384; idx += 256)
        Bs[(idx >> 7) * 129 + (idx & 127)] = B[idx];
    int r0 = blockIdx.x * 4;
    for (int idx = tid; idx < 512; idx += 256)
        As[idx] = A[(r0 + (idx >> 7)) * 128 + (idx & 127)];
    __syncthreads();
    int j = tid & 127, i0 = (tid >> 7) * 2;
    float c0 = 0.f, c1 = 0.f;
#pragma unroll 8
    for (int k = 0; k < 128; ++k) {
        float b = Bs[j * 129 + k];
        c0 = fmaf(As[i0 * 128 + k], b, c0);
        c1 = fmaf(As[i0 * 128 + 128 + k], b, c1);
    }
    g_QK[(r0 + i0) * 128 + j] = c0;
    g_QK[(r0 + i0 + 1) * 128 + j] = c1;
}

// fused per-step mid kernel: phase1 T1 = G@Vw (G = sum of 8 g_part2 slabs),
// global barrier (32 resident CTAs), phase2 Mt = split(QK @ T1).
__global__ void __launch_bounds__(256, 1)
kmid_kernel(const float* __restrict__ Vw) {
    extern __shared__ float ts[];
    float* Bs = ts;
    float* As = ts + 128 * 129;
    int tid = threadIdx.x;
    int r0 = blockIdx.x * 4;
    int j = tid & 127, i0 = (tid >> 7) * 2;

    // ---- phase 1: T1 = G @ Vw ----
    for (int idx = tid; idx < 16384; idx += 256)
        Bs[(idx >> 7) * 129 + (idx & 127)] = Vw[idx];
    for (int idx = tid; idx < 512; idx += 256) {
        int off = (r0 + (idx >> 7)) * 128 + (idx & 127);
        const float* p = g_part2 + off;
        float s = 0.f;
#pragma unroll
        for (int g = 0; g < 8; ++g) s += p[(size_t)g * 16384];
        As[idx] = s;
    }
    __syncthreads();
    {
        float c0 = 0.f, c1 = 0.f;
#pragma unroll 8
        for (int k = 0; k < 128; ++k) {
            float b = Bs[k * 129 + j];
            c0 = fmaf(As[i0 * 128 + k], b, c0);
            c1 = fmaf(As[i0 * 128 + 128 + k], b, c1);
        }
        g_T1[(r0 + i0) * 128 + j] = c0;
        g_T1[(r0 + i0 + 1) * 128 + j] = c1;
    }
    // ---- global barrier (all 32 CTAs resident; monotonic ticket) ----
    __threadfence();
    __syncthreads();
    if (tid == 0) {
        unsigned arrive = atomicAdd(&g_barrier, 1u);
        unsigned target = (arrive / 32u + 1u) * 32u;
        while (*reinterpret_cast<volatile unsigned*>(&g_barrier) < target)
            __nanosleep(64);
        __threadfence();
    }
    __syncthreads();
    // ---- phase 2: Mt = split(QK @ T1) ----
    for (int idx = tid; idx < 16384; idx += 256)
        Bs[(idx >> 7) * 129 + (idx & 127)] = __ldcg(g_T1 + idx);
    for (int idx = tid; idx < 512; idx += 256)
        As[idx] = g_QK[(r0 + (idx >> 7)) * 128 + (idx & 127)];
    __syncthreads();
    {
        float c0 = 0.f, c1 = 0.f;
#pragma unroll 8
        for (int k = 0; k < 128; ++k) {
            float b = Bs[k * 129 + j];
            c0 = fmaf(As[i0 * 128 + k], b, c0);
            c1 = fmaf(As[i0 * 128 + 128 + k], b, c1);
        }
        sp1(c0, &g_Mt_hi[j * 128 + r0 + i0], &g_Mt_lo[j * 128 + r0 + i0]);
        sp1(c1, &g_Mt_hi[j * 128 + r0 + i0 + 1], &g_Mt_lo[j * 128 + r0 + i0 + 1]);
    }
}

// ================= big fused kernel (HMMA + cp.async, 2-sync FF pipeline) =================
#define KC_RED  5120
#define KC_MRS  9216
#define KC_A    10240                  // Ahi 32K | Alo 32K
#define KC_B0   (KC_A + 65536)         // 32K (hi at +0, lo at +16384 for FF tiles)
#define KC_B1   (KC_B0 + 32768)
#define KC_F    (KC_B1 + 32768)        // Fhi 16K | Flo 16K
#define KC_SMEM (KC_F + 32768)         // 174080

__global__ void __launch_bounds__(256, 1)
kc_mma(const float* __restrict__ xin, int srcIsG,
       const float* __restrict__ ln1g, const float* __restrict__ ln1b,
       const float* __restrict__ ln2g, const float* __restrict__ ln2b,
       const float* __restrict__ b1, const float* __restrict__ b2,
       const float* __restrict__ outb, float* __restrict__ outp, int last) {
    extern __shared__ char sm[];
    uint32_t smb = smem_u32(sm);
    int tid = threadIdx.x, lane = tid & 31, wid = tid >> 5;
    int warp_m = wid & 1, warp_n = wid >> 1;
    int row0 = warp_m * 64 + (lane >> 2);
    int col0 = warp_n * 32 + (lane & 3) * 2;

    float* ln1gs = reinterpret_cast<float*>(sm);
    float* ln1bs = ln1gs + 128;
    float* ln2gs = ln1gs + 256;
    float* ln2bs = ln1gs + 384;
    float* b2s   = ln1gs + 512;
    float* outbs = ln1gs + 640;
    float* b1s   = ln1gs + 768;     // 512 floats
    float2* red  = reinterpret_cast<float2*>(sm + KC_RED);
    float2* mrs  = reinterpret_cast<float2*>(sm + KC_MRS);
    if (tid < 128) {
        ln1gs[tid] = ln1g[tid]; ln1bs[tid] = ln1b[tid];
        ln2gs[tid] = ln2g[tid]; ln2bs[tid] = ln2b[tid];
        b2s[tid] = b2[tid]; outbs[tid] = outb[tid];
    }
    b1s[tid] = b1[tid]; b1s[tid + 256] = b1[tid + 256];

    // prefetch Mt (hi -> B0, lo -> B1), overlapped with x load + LN1
    cp_tile256(smb + KC_B0, reinterpret_cast<const uint4*>(g_Mt_hi), 128, 16, tid);
    cp_tile256(smb + KC_B1, reinterpret_cast<const uint4*>(g_Mt_lo), 128, 16, tid);
    cpa_commit();

    // x in fragment layout
    size_t base = (size_t)blockIdx.x * 16384;
    const float* xt = (srcIsG ? g_x : xin) + base;
    float xr[4][4][4];
#pragma unroll
    for (int mi = 0; mi < 4; ++mi)
#pragma unroll
        for (int ni = 0; ni < 4; ++ni) {
            const float* p = xt + (row0 + mi * 16) * 128 + col0 + ni * 8;
            float2 a = *reinterpret_cast<const float2*>(p);
            float2 b = *reinterpret_cast<const float2*>(p + 8 * 128);
            xr[mi][ni][0] = a.x; xr[mi][ni][1] = a.y;
            xr[mi][ni][2] = b.x; xr[mi][ni][3] = b.y;
        }

    // A <- LN1(x)
    ln_acc(xr, ln1gs, ln1bs, sm + KC_A, sm + KC_A + 32768, red, mrs, warp_m, warp_n, lane, tid);
    cpa_wait<0>();
    __syncthreads();
    // x += h @ M
    mma_nt(xr, smb + KC_A, smb + KC_A + 32768, smb + KC_B0, smb + KC_B1, warp_m, warp_n, lane);
    __syncthreads();

    // prime FF pipeline: w1 sub-chunk 0 -> B0
    cp_tile256(smb + KC_B0,         reinterpret_cast<const uint4*>(g_w1t_hi), 64, 16, tid);
    cp_tile256(smb + KC_B0 + 16384, reinterpret_cast<const uint4*>(g_w1t_lo), 64, 16, tid);
    cpa_commit();

    // A <- LN2(x)
    ln_acc(xr, ln2gs, ln2bs, sm + KC_A, sm + KC_A + 32768, red, mrs, warp_m, warp_n, lane, tid);
    cpa_wait<0>();       // w1_0 landed
    __syncthreads();     // w1_0 visible

    // FF: 8 sub-chunks of 64 hidden units, double-buffered weights, 2 syncs/iter
#pragma unroll 1
    for (int c = 0; c < 8; ++c) {
        // prefetch w2_c -> B1 (overlaps mma1 + relu)
        cp_tile128(smb + KC_B1,         reinterpret_cast<const uint4*>(g_w2t_hi) + c * 8, 64, tid);
        cp_tile128(smb + KC_B1 + 16384, reinterpret_cast<const uint4*>(g_w2t_lo) + c * 8, 64, tid);
        cpa_commit();
        float u[4][2][4];
#pragma unroll
        for (int mi = 0; mi < 4; ++mi)
#pragma unroll
            for (int ni = 0; ni < 2; ++ni)
#pragma unroll
                for (int e = 0; e < 4; ++e) u[mi][ni][e] = 0.f;
        mma_n64(u, smb + KC_A, smb + KC_A + 32768, smb + KC_B0, smb + KC_B0 + 16384,
                warp_m, warp_n, lane);
        // bias + relu + split -> F
#pragma unroll
        for (int mi = 0; mi < 4; ++mi)
#pragma unroll
            for (int ni = 0; ni < 2; ++ni) {
                int hcol = warp_n * 16 + (lane & 3) * 2 + ni * 8;      // 0..63
                float bb0 = b1s[c * 64 + hcol], bb1 = b1s[c * 64 + hcol + 1];
                int r1 = row0 + mi * 16, r2 = r1 + 8;
                float f0 = fmaxf(u[mi][ni][0] + bb0, 0.f);
                float f1 = fmaxf(u[mi][ni][1] + bb1, 0.f);
                float f2 = fmaxf(u[mi][ni][2] + bb0, 0.f);
                float f3 = fmaxf(u[mi][ni][3] + bb1, 0.f);
                uint32_t h, l;
                uint32_t o1 = sw4_64(r1, hcol), o2 = sw4_64(r2, hcol);
                split2(f0, f1, h, l);
                *reinterpret_cast<uint32_t*>(sm + KC_F + o1) = h;
                *reinterpret_cast<uint32_t*>(sm + KC_F + 16384 + o1) = l;
                split2(f2, f3, h, l);
                *reinterpret_cast<uint32_t*>(sm + KC_F + o2) = h;
                *reinterpret_cast<uint32_t*>(sm + KC_F + 16384 + o2) = l;
            }
        cpa_wait<0>();       // w2_c landed
        __syncthreads();     // F + w2_c visible; B0 (w1_c) free
        // prefetch w1_{c+1} -> B0 (overlaps mma2); last iter: owt_hi if needed
        if (c < 7) {
            cp_tile256(smb + KC_B0,         reinterpret_cast<const uint4*>(g_w1t_hi) + (c + 1) * 1024, 64, 16, tid);
            cp_tile256(smb + KC_B0 + 16384, reinterpret_cast<const uint4*>(g_w1t_lo) + (c + 1) * 1024, 64, 16, tid);
        } else if (last) {
            cp_tile256(smb + KC_B0, reinterpret_cast<const uint4*>(g_owt_hi), 128, 16, tid);
        }
        cpa_commit();
        mma_k64(xr, smb + KC_F, smb + KC_F + 16384, smb + KC_B1, smb + KC_B1 + 16384,
                warp_m, warp_n, lane);
        cpa_wait<0>();       // w1_{c+1} (or owt_hi) landed
        __syncthreads();     // B1/F free; next tile visible
    }

    // + b2
#pragma unroll
    for (int mi = 0; mi < 4; ++mi)
#pragma unroll
        for (int ni = 0; ni < 4; ++ni) {
            int col = col0 + ni * 8;
            xr[mi][ni][0] += b2s[col];     xr[mi][ni][1] += b2s[col + 1];
            xr[mi][ni][2] += b2s[col];     xr[mi][ni][3] += b2s[col + 1];
        }

    if (!last) {
        // store x_new
        float* dst = g_x + base;
#pragma unroll
        for (int mi = 0; mi < 4; ++mi)
#pragma unroll
            for (int ni = 0; ni < 4; ++ni) {
                int r1 = row0 + mi * 16, col = col0 + ni * 8;
                *reinterpret_cast<float2*>(dst + r1 * 128 + col) =
                    make_float2(xr[mi][ni][0], xr[mi][ni][1]);
                *reinterpret_cast<float2*>(dst + (r1 + 8) * 128 + col) =
                    make_float2(xr[mi][ni][2], xr[mi][ni][3]);
            }
        // fused Gram partial for the NEXT step: h = LN1(x_new); part = h^T h
        ln_acc(xr, ln1gs, ln1bs, sm + KC_A, sm + KC_A + 32768, red, mrs, warp_m, warp_n, lane, tid);
        float ga[4][4][4];
#pragma unroll
        for (int mi = 0; mi < 4; ++mi)
#pragma unroll
            for (int ni = 0; ni < 4; ++ni)
#pragma unroll
                for (int e = 0; e < 4; ++e) ga[mi][ni][e] = 0.f;
        mma_tt(ga, smb + KC_A, smb + KC_A + 32768, warp_m, warp_n, lane);
        float* pdst = g_part + (size_t)blockIdx.x * 16384;
#pragma unroll
        for (int mi = 0; mi < 4; ++mi)
#pragma unroll
            for (int ni = 0; ni < 4; ++ni) {
                int r1 = row0 + mi * 16, col = col0 + ni * 8;
                *reinterpret_cast<float2*>(pdst + r1 * 128 + col) =
                    make_float2(ga[mi][ni][0], ga[mi][ni][1]);
                *reinterpret_cast<float2*>(pdst + (r1 + 8) * 128 + col) =
                    make_float2(ga[mi][ni][2], ga[mi][ni][3]);
            }
    } else {
        // out = x @ outw + outb  (owt_hi already landed in B0 at loop end)
        cp_tile256(smb + KC_B1, reinterpret_cast<const uint4*>(g_owt_lo), 128, 16, tid);
        cpa_commit();
        // split x -> A
#pragma unroll
        for (int mi = 0; mi < 4; ++mi)
#pragma unroll
            for (int ni = 0; ni < 4; ++ni) {
                int col = col0 + ni * 8;
                int r1 = row0 + mi * 16, r2 = r1 + 8;
                uint32_t h, l;
                uint32_t o1 = sw4(r1, col), o2 = sw4(r2, col);
                split2(xr[mi][ni][0], xr[mi][ni][1], h, l);
                *reinterpret_cast<uint32_t*>(sm + KC_A + o1) = h;
                *reinterpret_cast<uint32_t*>(sm + KC_A + 32768 + o1) = l;
                split2(xr[mi][ni][2], xr[mi][ni][3], h, l);
                *reinterpret_cast<uint32_t*>(sm + KC_A + o2) = h;
                *reinterpret_cast<uint32_t*>(sm + KC_A + 32768 + o2) = l;
            }
        cpa_wait<0>();
        __syncthreads();
        float o[4][4][4];
#pragma unroll
        for (int mi = 0; mi < 4; ++mi)
#pragma unroll
            for (int ni = 0; ni < 4; ++ni)
#pragma unroll
                for (int e = 0; e < 4; ++e) o[mi][ni][e] = 0.f;
        mma_nt(o, smb + KC_A, smb + KC_A + 32768, smb + KC_B0, smb + KC_B1, warp_m, warp_n, lane);
        float* dst = outp + base;
#pragma unroll
        for (int mi = 0; mi < 4; ++mi)
#pragma unroll
            for (int ni = 0; ni < 4; ++ni) {
                int r1 = row0 + mi * 16, col = col0 + ni * 8;
                *reinterpret_cast<float2*>(dst + r1 * 128 + col) =
                    make_float2(o[mi][ni][0] + outbs[col], o[mi][ni][1] + outbs[col + 1]);
                *reinterpret_cast<float2*>(dst + (r1 + 8) * 128 + col) =
                    make_float2(o[mi][ni][2] + outbs[col], o[mi][ni][3] + outbs[col + 1]);
            }
    }
}

// ============================ host launcher ============================
extern "C" void kernel_launch(void* const* d_in, const int* in_sizes, int n_in,
                              void* d_out, int out_size) {
    (void)in_sizes; (void)n_in; (void)out_size;
    const float* x    = (const float*)d_in[0];
    const float* Kw   = (const float*)d_in[1];
    const float* Qw   = (const float*)d_in[2];
    const float* Vw   = (const float*)d_in[3];
    const float* ln1g = (const float*)d_in[4];
    const float* ln1b = (const float*)d_in[5];
    const float* ln2g = (const float*)d_in[6];
    const float* ln2b = (const float*)d_in[7];
    const float* w1   = (const float*)d_in[8];
    const float* b1   = (const float*)d_in[9];
    const float* w2   = (const float*)d_in[10];
    const float* b2   = (const float*)d_in[11];
    const float* outw = (const float*)d_in[12];
    const float* outb = (const float*)d_in[13];
    float* out = (float*)d_out;

    cudaFuncSetAttribute(kc_mma, cudaFuncAttributeMaxDynamicSharedMemorySize, KC_SMEM);
    cudaFuncSetAttribute(kgram0, cudaFuncAttributeMaxDynamicSharedMemorySize, KG_SMEM);
    cudaFuncSetAttribute(kqk_kernel, cudaFuncAttributeMaxDynamicSharedMemorySize, TS_SMEM);
    cudaFuncSetAttribute(kmid_kernel, cudaFuncAttributeMaxDynamicSharedMemorySize, TS_SMEM);

    kprep_kernel<<<576, 256>>>(w1, w2, outw);
    kqk_kernel<<<32, 256, TS_SMEM>>>(Qw, Kw);         // QK = Qw @ Kw^T
    kgram0<<<NTILESm, 256, KG_SMEM>>>(x, ln1g, ln1b);

    for (int t = 0; t < 4; ++t) {
        int srcIsG = (t != 0);
        kred1_kernel<<<512, 256>>>();                 // 1024 -> 8 partials
        kmid_kernel<<<32, 256, TS_SMEM>>>(Vw);        // T1 = G@Vw ; Mt = split(QK@T1)
        kc_mma<<<NTILESm, 256, KC_SMEM>>>(x, srcIsG, ln1g, ln1b, ln2g, ln2b,
                                          b1, b2, outb, out, t == 3);
    }
}